// round 7
// baseline (speedup 1.0000x reference)
#include <cuda_runtime.h>
#include <cuda_bf16.h>
#include <math.h>
#include <stdint.h>

#define BB   4
#define CC   1024
#define DD   1024
#define HH   16
#define CD   (CC*DD)          // 1048576
#define BCD  (BB*CD)          // 4194304
#define H1SZ (BB*4096*1024)   // 16777216

// ---------------- scratch (static __device__ arrays; no runtime alloc) ---------------
__device__ __nv_bfloat16 g_ln_hi[3*BCD],  g_ln_lo[3*BCD];    // lnq/lnk/lnv planes
__device__ __nv_bfloat16 g_qkv_hi[3*BCD], g_qkv_lo[3*BCD];   // q/k/v planes
__device__ __nv_bfloat16 g_w_hi[3*CD],    g_w_lo[3*CD];      // wq/wk/wv planes
__device__ __nv_bfloat16 g_c1w_hi[4*CD],  g_c1w_lo[4*CD];
__device__ __nv_bfloat16 g_c2w_hi[4*CD],  g_c2w_lo[4*CD];
__device__ __nv_bfloat16 g_xl_hi[BCD],    g_xl_lo[BCD];
__device__ __nv_bfloat16 g_h1_hi[H1SZ],   g_h1_lo[H1SZ];
__device__ float g_x[BCD];          // x1 + attention out (residual)
__device__ float g_bqkv[3*1024];    // gathered q/k/v biases

// =====================================================================================
// helpers
// =====================================================================================
__device__ __forceinline__ uint32_t smem_u32(const void* p) {
    uint32_t a;
    asm("{ .reg .u64 t; cvta.to.shared.u64 t, %1; cvt.u32.u64 %0, t; }" : "=r"(a) : "l"(p));
    return a;
}
__device__ __forceinline__ void cpa16(uint32_t s, const void* g) {
    asm volatile("cp.async.cg.shared.global [%0], [%1], 16;" :: "r"(s), "l"(g));
}
__device__ __forceinline__ void ldsm4(uint32_t addr, uint32_t& r0, uint32_t& r1,
                                      uint32_t& r2, uint32_t& r3) {
    asm volatile("ldmatrix.sync.aligned.m8n8.x4.shared.b16 {%0,%1,%2,%3}, [%4];"
                 : "=r"(r0), "=r"(r1), "=r"(r2), "=r"(r3) : "r"(addr));
}
__device__ __forceinline__ void ldsm4t(uint32_t addr, uint32_t& r0, uint32_t& r1,
                                       uint32_t& r2, uint32_t& r3) {
    asm volatile("ldmatrix.sync.aligned.m8n8.x4.trans.shared.b16 {%0,%1,%2,%3}, [%4];"
                 : "=r"(r0), "=r"(r1), "=r"(r2), "=r"(r3) : "r"(addr));
}
__device__ __forceinline__ void mma16816(float* c, const uint32_t* a, const uint32_t* b) {
    asm volatile(
        "mma.sync.aligned.m16n8k16.row.col.f32.bf16.bf16.f32 "
        "{%0,%1,%2,%3}, {%4,%5,%6,%7}, {%8,%9}, {%0,%1,%2,%3};"
        : "+f"(c[0]), "+f"(c[1]), "+f"(c[2]), "+f"(c[3])
        : "r"(a[0]), "r"(a[1]), "r"(a[2]), "r"(a[3]), "r"(b[0]), "r"(b[1]));
}
__device__ __forceinline__ void split1(float v, __nv_bfloat16& h, __nv_bfloat16& l) {
    h = __float2bfloat16(v);
    l = __float2bfloat16(v - __bfloat162float(h));
}

// =====================================================================================
// Generic tensor-core GEMM (pre-split bf16 hi/lo operands, 3-MMA fp32-class accuracy)
// BK=64, 3-stage cp.async pipeline, 3-pass MMA ordering (independent acc chains).
// =====================================================================================
template<int BN, bool BTRANS, bool ACONV, bool BIAS_M, bool BIAS_N,
         bool GELUF, bool ADDF, bool SCALEF, bool OSPLIT>
__global__ void __launch_bounds__(256, 1)
tc2_gemm(const void* Ahv, const __nv_bfloat16* Alo, long strideA, int lda,
         const __nv_bfloat16* Bhi, const __nv_bfloat16* Blo,
         int bDiv, long bHi, long bLo, int ldb,
         float* Cf, __nv_bfloat16* Chi, __nv_bfloat16* Clo,
         int cDiv, long cHi, long cLo, int ldc,
         const float* Add, const float* bias, int biasZ,
         float alpha, int M, int N, int K)
{
    constexpr int BK  = 64;
    constexpr int SKA = 72;                        // K-contig smem row stride
    constexpr int SN  = BN + 8;                    // trans-B smem row stride
    constexpr int ASZ = 128 * SKA;                 // elems per A plane
    constexpr int BSZ = BTRANS ? (BK * SN) : (BN * SKA);
    constexpr int STAGE = 2 * ASZ + 2 * BSZ;       // elems per stage
    constexpr int NW_M = (BN == 128) ? 2 : 4;
    constexpr int NW_N = 8 / NW_M;
    constexpr int WTM = 128 / NW_M;
    constexpr int WTN = BN / NW_N;
    constexpr int MF = WTM / 16;
    constexpr int NF = WTN / 8;

    extern __shared__ __nv_bfloat16 sm[];

    const int tid = threadIdx.x, wid = tid >> 5, lid = tid & 31;
    const int wm = wid / NW_N, wn = wid % NW_N;
    const int z = blockIdx.z;
    const int row0 = blockIdx.y * 128, col0 = blockIdx.x * BN;

    const __nv_bfloat16* Ahi = ACONV ? nullptr : ((const __nv_bfloat16*)Ahv + (long)z * strideA);
    const __nv_bfloat16* Alz = ACONV ? nullptr : (Alo + (long)z * strideA);
    const float* Af = ACONV ? ((const float*)Ahv + (long)z * strideA) : nullptr;
    Bhi += (long)(z / bDiv) * bHi + (long)(z % bDiv) * bLo;
    Blo += (long)(z / bDiv) * bHi + (long)(z % bDiv) * bLo;
    const long coff = (long)(z / cDiv) * cHi + (long)(z % cDiv) * cLo;
    if (BIAS_N || BIAS_M) bias += (long)z * biasZ;

    const uint32_t smBase = smem_u32(sm);
    const int nIt = K / BK;

    float acc[MF][NF][4];
#pragma unroll
    for (int i = 0; i < MF; i++)
#pragma unroll
        for (int j = 0; j < NF; j++)
#pragma unroll
            for (int r = 0; r < 4; r++) acc[i][j][r] = 0.f;

    float4 av[8];  // ACONV staging (128x64 fp32 tile = 8 float4/thread)

    auto issueTile = [&](int it, int st) {
        const int k0 = it * BK;
        const uint32_t sbase = smBase + (uint32_t)(st * STAGE) * 2;
        if (!ACONV) {
#pragma unroll
            for (int pl = 0; pl < 2; pl++) {
                const __nv_bfloat16* Ag = pl ? Alz : Ahi;
                const uint32_t sd = sbase + (uint32_t)(pl * ASZ) * 2;
#pragma unroll
                for (int i = 0; i < 4; i++) {
                    int idx = tid + (i << 8);
                    int r = idx >> 3, c8 = (idx & 7) << 3;
                    cpa16(sd + (uint32_t)(r * SKA + c8) * 2,
                          Ag + (long)(row0 + r) * lda + k0 + c8);
                }
            }
        }
        if (BTRANS) {
            constexpr int CH = BK * BN / 8 / 256;  // 4 (BN=128) / 2 (BN=64)
#pragma unroll
            for (int pl = 0; pl < 2; pl++) {
                const __nv_bfloat16* Bg = pl ? Blo : Bhi;
                const uint32_t sd = sbase + (uint32_t)(2 * ASZ + pl * BSZ) * 2;
#pragma unroll
                for (int i = 0; i < CH; i++) {
                    int idx = tid + (i << 8);
                    int k = idx / (BN / 8), c8 = (idx % (BN / 8)) << 3;
                    cpa16(sd + (uint32_t)(k * SN + c8) * 2,
                          Bg + (long)(k0 + k) * ldb + col0 + c8);
                }
            }
        } else {
#pragma unroll
            for (int pl = 0; pl < 2; pl++) {
                const __nv_bfloat16* Bg = pl ? Blo : Bhi;
                const uint32_t sd = sbase + (uint32_t)(2 * ASZ + pl * BSZ) * 2;
#pragma unroll
                for (int i = 0; i < BN / 32; i++) {
                    int idx = tid + (i << 8);
                    int r = idx >> 3, c8 = (idx & 7) << 3;
                    cpa16(sd + (uint32_t)(r * SKA + c8) * 2,
                          Bg + (long)(col0 + r) * ldb + k0 + c8);
                }
            }
        }
    };
    auto ldgA = [&](int it) {
        const int k0 = it * BK;
#pragma unroll
        for (int i = 0; i < 8; i++) {
            int idx = tid + (i << 8);
            int r = idx >> 4, c4 = (idx & 15) << 2;
            av[i] = *(const float4*)(Af + (long)(row0 + r) * lda + k0 + c4);
        }
    };
    auto stsA = [&](int st) {
        __nv_bfloat16* sAhi = sm + st * STAGE;
        __nv_bfloat16* sAlo = sAhi + ASZ;
#pragma unroll
        for (int i = 0; i < 8; i++) {
            int idx = tid + (i << 8);
            int r = idx >> 4, c4 = (idx & 15) << 2;
            __nv_bfloat16 h[4], l[4];
            split1(av[i].x, h[0], l[0]); split1(av[i].y, h[1], l[1]);
            split1(av[i].z, h[2], l[2]); split1(av[i].w, h[3], l[3]);
            *(uint2*)(sAhi + r * SKA + c4) = *(uint2*)h;
            *(uint2*)(sAlo + r * SKA + c4) = *(uint2*)l;
        }
    };

    if (ACONV) { ldgA(0); stsA(0); }
    issueTile(0, 0);
    asm volatile("cp.async.commit_group;");

    for (int it = 0; it < nIt; it++) {
        const int s = it % 3;
        if (it + 1 < nIt) {
            if (ACONV) ldgA(it + 1);
            issueTile(it + 1, (it + 1) % 3);
            asm volatile("cp.async.commit_group;");
            asm volatile("cp.async.wait_group 1;");
        } else {
            asm volatile("cp.async.wait_group 0;");
        }
        __syncthreads();

        const uint32_t base = smBase + (uint32_t)(s * STAGE) * 2;
        const uint32_t aHiB = base, aLoB = base + ASZ * 2;
        const uint32_t bHiB = base + 2 * ASZ * 2, bLoB = bHiB + BSZ * 2;

#pragma unroll
        for (int ks = 0; ks < 4; ks++) {
            uint32_t ah[MF][4], al[MF][4], bh[NF][2], bl[NF][2];
#pragma unroll
            for (int mf = 0; mf < MF; mf++) {
                uint32_t off = (uint32_t)((wm * WTM + mf * 16 + (lid & 15)) * SKA
                                          + ks * 16 + (lid >> 4) * 8) * 2;
                ldsm4(aHiB + off, ah[mf][0], ah[mf][1], ah[mf][2], ah[mf][3]);
                ldsm4(aLoB + off, al[mf][0], al[mf][1], al[mf][2], al[mf][3]);
            }
            if (BTRANS) {
#pragma unroll
                for (int p = 0; p < NF / 2; p++) {
                    uint32_t off = (uint32_t)((ks * 16 + (lid & 15)) * SN
                                              + wn * WTN + p * 16 + (lid >> 4) * 8) * 2;
                    ldsm4t(bHiB + off, bh[2*p][0], bh[2*p][1], bh[2*p+1][0], bh[2*p+1][1]);
                    ldsm4t(bLoB + off, bl[2*p][0], bl[2*p][1], bl[2*p+1][0], bl[2*p+1][1]);
                }
            } else {
#pragma unroll
                for (int p = 0; p < NF / 2; p++) {
                    uint32_t off = (uint32_t)((wn * WTN + p * 16 + (lid & 7) + (lid >> 4) * 8) * SKA
                                              + ks * 16 + ((lid >> 3) & 1) * 8) * 2;
                    ldsm4(bHiB + off, bh[2*p][0], bh[2*p][1], bh[2*p+1][0], bh[2*p+1][1]);
                    ldsm4(bLoB + off, bl[2*p][0], bl[2*p][1], bl[2*p+1][0], bl[2*p+1][1]);
                }
            }
            // 3-pass ordering: MF*NF independent accumulators per pass
#pragma unroll
            for (int mf = 0; mf < MF; mf++)
#pragma unroll
                for (int nf = 0; nf < NF; nf++)
                    mma16816(acc[mf][nf], ah[mf], bh[nf]);
#pragma unroll
            for (int mf = 0; mf < MF; mf++)
#pragma unroll
                for (int nf = 0; nf < NF; nf++)
                    mma16816(acc[mf][nf], ah[mf], bl[nf]);
#pragma unroll
            for (int mf = 0; mf < MF; mf++)
#pragma unroll
                for (int nf = 0; nf < NF; nf++)
                    mma16816(acc[mf][nf], al[mf], bh[nf]);
        }
        if (ACONV && it + 1 < nIt) stsA((it + 1) % 3);
    }

    // ---- epilogue ----
    float* Cp = OSPLIT ? nullptr : (Cf + coff);
    __nv_bfloat16* ChP = OSPLIT ? (Chi + coff) : nullptr;
    __nv_bfloat16* ClP = OSPLIT ? (Clo + coff) : nullptr;
    const float* Ap2 = ADDF ? (Add + coff) : nullptr;
    const int rBase = row0 + wm * WTM + (lid >> 2);
    const int cBase = col0 + wn * WTN + (lid & 3) * 2;
#pragma unroll
    for (int mf = 0; mf < MF; mf++) {
#pragma unroll
        for (int half = 0; half < 2; half++) {
            const int gr = rBase + mf * 16 + half * 8;
            const float bm = BIAS_M ? bias[gr] : 0.f;
#pragma unroll
            for (int nf = 0; nf < NF; nf++) {
                const int gc = cBase + nf * 8;
                float v0 = acc[mf][nf][half * 2 + 0];
                float v1 = acc[mf][nf][half * 2 + 1];
                if (SCALEF) { v0 *= alpha; v1 *= alpha; }
                if (BIAS_M) { v0 += bm; v1 += bm; }
                if (BIAS_N) { v0 += bias[gc]; v1 += bias[gc + 1]; }
                if (GELUF) {
                    v0 = 0.5f * v0 * (1.0f + erff(v0 * 0.70710678118654752f));
                    v1 = 0.5f * v1 * (1.0f + erff(v1 * 0.70710678118654752f));
                }
                long off = (long)gr * ldc + gc;
                if (ADDF) { v0 += Ap2[off]; v1 += Ap2[off + 1]; }
                if (OSPLIT) {
                    __nv_bfloat16 h0, l0, h1, l1;
                    split1(v0, h0, l0); split1(v1, h1, l1);
                    __nv_bfloat16 hp[2] = {h0, h1}, lp[2] = {l0, l1};
                    *(uint32_t*)(ChP + off) = *(uint32_t*)hp;
                    *(uint32_t*)(ClP + off) = *(uint32_t*)lp;
                } else {
                    *(float2*)(Cp + off) = make_float2(v0, v1);
                }
            }
        }
    }
}

// =====================================================================================
// Fused QK^T * 0.125 + softmax-one -> attn out. grid (32, 64), 256 threads.
// Q fragments reloaded per chunk (no spill); 3-pass MMA ordering.
// =====================================================================================
__global__ void __launch_bounds__(256, 1)
qk_softmax(const __nv_bfloat16* __restrict__ qHi, const __nv_bfloat16* __restrict__ qLo,
           const __nv_bfloat16* __restrict__ kHi, const __nv_bfloat16* __restrict__ kLo,
           float* __restrict__ attn)
{
    constexpr int SK = 72;
    constexpr int QPL = 32 * SK;
    constexpr int KPL = 128 * SK;
    extern __shared__ __nv_bfloat16 sm[];
    float* redA = (float*)(sm + 2 * QPL + 4 * KPL);
    float* redB = redA + 32 * 9;

    const int tid = threadIdx.x, wid = tid >> 5, lid = tid & 31;
    const int z = blockIdx.y;
    const int row0 = blockIdx.x * 32;
    const __nv_bfloat16* Qh = qHi + (long)z * 65536;
    const __nv_bfloat16* Ql = qLo + (long)z * 65536;
    const __nv_bfloat16* Kh = kHi + (long)z * 65536;
    const __nv_bfloat16* Kl = kLo + (long)z * 65536;
    attn += (long)z * 1048576;

    const uint32_t smBase = smem_u32(sm);

    {
        int r = tid >> 3, c8 = (tid & 7) << 3;
        cpa16(smBase + (uint32_t)(r * SK + c8) * 2,        Qh + (long)(row0 + r) * 64 + c8);
        cpa16(smBase + (uint32_t)(QPL + r * SK + c8) * 2,  Ql + (long)(row0 + r) * 64 + c8);
    }
    auto issueK = [&](int ch, int st) {
        const uint32_t sb = smBase + (uint32_t)(2 * QPL + st * 2 * KPL) * 2;
#pragma unroll
        for (int pl = 0; pl < 2; pl++) {
            const __nv_bfloat16* Kg = pl ? Kl : Kh;
            const uint32_t sd = sb + (uint32_t)(pl * KPL) * 2;
#pragma unroll
            for (int i = 0; i < 4; i++) {
                int idx = tid + (i << 8);
                int r = idx >> 3, c8 = (idx & 7) << 3;
                cpa16(sd + (uint32_t)(r * SK + c8) * 2,
                      Kg + (long)(ch * 128 + r) * 64 + c8);
            }
        }
    };
    issueK(0, 0);
    asm volatile("cp.async.commit_group;");

    float acc[2][8][2][4];
#pragma unroll
    for (int mf = 0; mf < 2; mf++)
#pragma unroll
        for (int ch = 0; ch < 8; ch++)
#pragma unroll
            for (int nf = 0; nf < 2; nf++)
#pragma unroll
                for (int r = 0; r < 4; r++) acc[mf][ch][nf][r] = 0.f;

    for (int ch = 0; ch < 8; ch++) {
        asm volatile("cp.async.wait_group 0;");
        __syncthreads();
        if (ch + 1 < 8) {
            issueK(ch + 1, (ch + 1) & 1);
            asm volatile("cp.async.commit_group;");
        }
        const int st = ch & 1;
        const uint32_t kHiB = smBase + (uint32_t)(2 * QPL + st * 2 * KPL) * 2;
        const uint32_t kLoB = kHiB + (uint32_t)KPL * 2;
#pragma unroll
        for (int ks = 0; ks < 4; ks++) {
            uint32_t aH[2][4], aL[2][4], bh[2][2], bl[2][2];
#pragma unroll
            for (int mf = 0; mf < 2; mf++) {
                uint32_t off = (uint32_t)((mf * 16 + (lid & 15)) * SK
                                          + ks * 16 + (lid >> 4) * 8) * 2;
                ldsm4(smBase + off,           aH[mf][0], aH[mf][1], aH[mf][2], aH[mf][3]);
                ldsm4(smBase + QPL * 2 + off, aL[mf][0], aL[mf][1], aL[mf][2], aL[mf][3]);
            }
            uint32_t offB = (uint32_t)((wid * 16 + (lid & 7) + (lid >> 4) * 8) * SK
                                       + ks * 16 + ((lid >> 3) & 1) * 8) * 2;
            ldsm4(kHiB + offB, bh[0][0], bh[0][1], bh[1][0], bh[1][1]);
            ldsm4(kLoB + offB, bl[0][0], bl[0][1], bl[1][0], bl[1][1]);
#pragma unroll
            for (int mf = 0; mf < 2; mf++)
#pragma unroll
                for (int nf = 0; nf < 2; nf++)
                    mma16816(acc[mf][ch][nf], aH[mf], bh[nf]);
#pragma unroll
            for (int mf = 0; mf < 2; mf++)
#pragma unroll
                for (int nf = 0; nf < 2; nf++)
                    mma16816(acc[mf][ch][nf], aH[mf], bl[nf]);
#pragma unroll
            for (int mf = 0; mf < 2; mf++)
#pragma unroll
                for (int nf = 0; nf < 2; nf++)
                    mma16816(acc[mf][ch][nf], aL[mf], bh[nf]);
        }
    }

    // ---- softmax-one across full 1024-col rows ----
    const int rq = lid >> 2, cq = lid & 3;
#pragma unroll
    for (int mf = 0; mf < 2; mf++)
#pragma unroll
        for (int ch = 0; ch < 8; ch++)
#pragma unroll
            for (int nf = 0; nf < 2; nf++)
#pragma unroll
                for (int r = 0; r < 4; r++) acc[mf][ch][nf][r] *= 0.125f;

    float mx[2][2];
#pragma unroll
    for (int mf = 0; mf < 2; mf++)
#pragma unroll
        for (int half = 0; half < 2; half++) {
            float m = -1e30f;
#pragma unroll
            for (int ch = 0; ch < 8; ch++)
#pragma unroll
                for (int nf = 0; nf < 2; nf++)
                    m = fmaxf(m, fmaxf(acc[mf][ch][nf][half*2], acc[mf][ch][nf][half*2+1]));
            m = fmaxf(m, __shfl_xor_sync(0xffffffffu, m, 1));
            m = fmaxf(m, __shfl_xor_sync(0xffffffffu, m, 2));
            mx[mf][half] = m;
        }
    if (cq == 0) {
#pragma unroll
        for (int mf = 0; mf < 2; mf++)
#pragma unroll
            for (int half = 0; half < 2; half++)
                redA[(mf * 16 + half * 8 + rq) * 9 + wid] = mx[mf][half];
    }
    __syncthreads();
#pragma unroll
    for (int mf = 0; mf < 2; mf++)
#pragma unroll
        for (int half = 0; half < 2; half++) {
            float m = -1e30f;
            const float* rr = redA + (mf * 16 + half * 8 + rq) * 9;
#pragma unroll
            for (int w = 0; w < 8; w++) m = fmaxf(m, rr[w]);
            mx[mf][half] = m;
        }

    float sum[2][2] = {{0.f, 0.f}, {0.f, 0.f}};
#pragma unroll
    for (int mf = 0; mf < 2; mf++)
#pragma unroll
        for (int half = 0; half < 2; half++) {
            const float m = mx[mf][half];
            float s = 0.f;
#pragma unroll
            for (int ch = 0; ch < 8; ch++)
#pragma unroll
                for (int nf = 0; nf < 2; nf++) {
                    float e0 = __expf(acc[mf][ch][nf][half*2]     - m);
                    float e1 = __expf(acc[mf][ch][nf][half*2 + 1] - m);
                    acc[mf][ch][nf][half*2]     = e0;
                    acc[mf][ch][nf][half*2 + 1] = e1;
                    s += e0 + e1;
                }
            s += __shfl_xor_sync(0xffffffffu, s, 1);
            s += __shfl_xor_sync(0xffffffffu, s, 2);
            sum[mf][half] = s;
        }
    if (cq == 0) {
#pragma unroll
        for (int mf = 0; mf < 2; mf++)
#pragma unroll
            for (int half = 0; half < 2; half++)
                redB[(mf * 16 + half * 8 + rq) * 9 + wid] = sum[mf][half];
    }
    __syncthreads();
#pragma unroll
    for (int mf = 0; mf < 2; mf++)
#pragma unroll
        for (int half = 0; half < 2; half++) {
            float s = 0.f;
            const float* rr = redB + (mf * 16 + half * 8 + rq) * 9;
#pragma unroll
            for (int w = 0; w < 8; w++) s += rr[w];
            sum[mf][half] = 1.0f / (1.0f + s);
        }

#pragma unroll
    for (int mf = 0; mf < 2; mf++)
#pragma unroll
        for (int half = 0; half < 2; half++) {
            const int gr = row0 + mf * 16 + half * 8 + rq;
            const float inv = sum[mf][half];
#pragma unroll
            for (int ch = 0; ch < 8; ch++)
#pragma unroll
                for (int nf = 0; nf < 2; nf++) {
                    const int gc = ch * 128 + wid * 16 + nf * 8 + cq * 2;
                    *(float2*)(attn + (long)gr * 1024 + gc) =
                        make_float2(acc[mf][ch][nf][half*2] * inv,
                                    acc[mf][ch][nf][half*2+1] * inv);
                }
        }
}

// =====================================================================================
__global__ void cvt_kernel(const float* __restrict__ s, __nv_bfloat16* __restrict__ hi,
                           __nv_bfloat16* __restrict__ lo, int n4)
{
    int i = blockIdx.x * 256 + threadIdx.x;
    if (i >= n4) return;
    float4 v = ((const float4*)s)[i];
    __nv_bfloat16 h[4], l[4];
    split1(v.x, h[0], l[0]); split1(v.y, h[1], l[1]);
    split1(v.z, h[2], l[2]); split1(v.w, h[3], l[3]);
    ((uint2*)hi)[i] = *(uint2*)h;
    ((uint2*)lo)[i] = *(uint2*)l;
}

__global__ void bias_gather(const float* a, const float* b, const float* c, float* o)
{
    const float* src[3] = {a, b, c};
    o[blockIdx.x * 1024 + threadIdx.x] = src[blockIdx.x][threadIdx.x];
}

// =====================================================================================
__global__ void ln3_kernel(const float* __restrict__ x, int nOut,
    const float* __restrict__ w0, const float* __restrict__ b0,
    const float* __restrict__ w1, const float* __restrict__ b1,
    const float* __restrict__ w2, const float* __restrict__ b2,
    __nv_bfloat16* __restrict__ oHi, __nv_bfloat16* __restrict__ oLo)
{
    const int dx   = threadIdx.x & 31;
    const int lane = threadIdx.x >> 5;
    const int d    = blockIdx.x * 32 + dx;
    const long base = (long)blockIdx.y * CD + d;

    float s = 0.f, ss = 0.f;
    for (int c = lane; c < CC; c += 8) {
        float v = x[base + (long)c * DD];
        s += v; ss += v * v;
    }
    __shared__ float sS[8][33], sQ[8][33];
    sS[lane][dx] = s; sQ[lane][dx] = ss;
    __syncthreads();
    if (lane == 0) {
        float ts = 0.f, tq = 0.f;
        #pragma unroll
        for (int i = 0; i < 8; i++) { ts += sS[i][dx]; tq += sQ[i][dx]; }
        float mean = ts * (1.0f / CC);
        float var  = tq * (1.0f / CC) - mean * mean;
        sS[0][dx] = mean;
        sQ[0][dx] = rsqrtf(var + 1e-6f);
    }
    __syncthreads();
    const float mean = sS[0][dx];
    const float rstd = sQ[0][dx];
    const float* W[3] = {w0, w1, w2};
    const float* Bv[3] = {b0, b1, b2};
    for (int c = lane; c < CC; c += 8) {
        long idx = base + (long)c * DD;
        float xn = (x[idx] - mean) * rstd;
        for (int p = 0; p < nOut; p++) {
            float v = W[p][c] * xn + Bv[p][c];
            __nv_bfloat16 h, l;
            split1(v, h, l);
            oHi[(long)p * BCD + idx] = h;
            oLo[(long)p * BCD + idx] = l;
        }
    }
}

// =====================================================================================
extern "C" void kernel_launch(void* const* d_in, const int* in_sizes, int n_in,
                              void* d_out, int out_size)
{
    const float* x1      = (const float*)d_in[0];
    const float* lnq_w   = (const float*)d_in[1];
    const float* lnq_b   = (const float*)d_in[2];
    const float* lnk_w   = (const float*)d_in[3];
    const float* lnk_b   = (const float*)d_in[4];
    const float* lnv_w   = (const float*)d_in[5];
    const float* lnv_b   = (const float*)d_in[6];
    const float* wq      = (const float*)d_in[7];
    const float* bq      = (const float*)d_in[8];
    const float* wk      = (const float*)d_in[9];
    const float* bk      = (const float*)d_in[10];
    const float* wv      = (const float*)d_in[11];
    const float* bv      = (const float*)d_in[12];
    const float* ffnln_w = (const float*)d_in[13];
    const float* ffnln_b = (const float*)d_in[14];
    const float* conv1_w = (const float*)d_in[15];
    const float* conv1_b = (const float*)d_in[16];
    const float* conv2_w = (const float*)d_in[17];
    const float* conv2_b = (const float*)d_in[18];

    __nv_bfloat16 *lnHi, *lnLo, *qkvHi, *qkvLo, *wHi, *wLo;
    __nv_bfloat16 *c1wHi, *c1wLo, *c2wHi, *c2wLo, *xlHi, *xlLo, *h1Hi, *h1Lo;
    float *xb, *bqkv;
    cudaGetSymbolAddress((void**)&lnHi,  g_ln_hi);   cudaGetSymbolAddress((void**)&lnLo,  g_ln_lo);
    cudaGetSymbolAddress((void**)&qkvHi, g_qkv_hi);  cudaGetSymbolAddress((void**)&qkvLo, g_qkv_lo);
    cudaGetSymbolAddress((void**)&wHi,   g_w_hi);    cudaGetSymbolAddress((void**)&wLo,   g_w_lo);
    cudaGetSymbolAddress((void**)&c1wHi, g_c1w_hi);  cudaGetSymbolAddress((void**)&c1wLo, g_c1w_lo);
    cudaGetSymbolAddress((void**)&c2wHi, g_c2w_hi);  cudaGetSymbolAddress((void**)&c2wLo, g_c2w_lo);
    cudaGetSymbolAddress((void**)&xlHi,  g_xl_hi);   cudaGetSymbolAddress((void**)&xlLo,  g_xl_lo);
    cudaGetSymbolAddress((void**)&h1Hi,  g_h1_hi);   cudaGetSymbolAddress((void**)&h1Lo,  g_h1_lo);
    cudaGetSymbolAddress((void**)&xb,    g_x);
    cudaGetSymbolAddress((void**)&bqkv,  g_bqkv);

    float* outx = (float*)d_out;
    float* attn = outx + (long)BCD;

    auto kQKV = tc2_gemm<128, false, false, false, true,  false, false, false, true >;
    auto kPV  = tc2_gemm<64,  true,  true,  false, false, false, true,  false, false>;
    auto kC1  = tc2_gemm<128, true,  false, true,  false, true,  false, false, true >;
    auto kC2  = tc2_gemm<128, true,  false, true,  false, false, true,  false, false>;
    // BK=64, 3 stages
    const int SM_BT128 = 3 * (2 * 128 * 72 + 2 * 128 * 72) * 2;  // 221184
    const int SM_TR128 = 3 * (2 * 128 * 72 + 2 * 64 * 136) * 2;  // 215040
    const int SM_TR64  = 3 * (2 * 128 * 72 + 2 * 64 * 72) * 2;   // 165888
    const int SM_QS = (2 * 32 * 72 + 4 * 128 * 72) * 2 + 2 * 32 * 9 * 4;  // 85248
    cudaFuncSetAttribute(kQKV, cudaFuncAttributeMaxDynamicSharedMemorySize, SM_BT128);
    cudaFuncSetAttribute(kPV,  cudaFuncAttributeMaxDynamicSharedMemorySize, SM_TR64);
    cudaFuncSetAttribute(kC1,  cudaFuncAttributeMaxDynamicSharedMemorySize, SM_TR128);
    cudaFuncSetAttribute(kC2,  cudaFuncAttributeMaxDynamicSharedMemorySize, SM_TR128);
    cudaFuncSetAttribute(qk_softmax, cudaFuncAttributeMaxDynamicSharedMemorySize, SM_QS);

    // 0) pre-split weights + gather qkv biases
    cvt_kernel<<<CD / 4 / 256, 256>>>(wq, wHi,          wLo,          CD / 4);
    cvt_kernel<<<CD / 4 / 256, 256>>>(wk, wHi + CD,     wLo + CD,     CD / 4);
    cvt_kernel<<<CD / 4 / 256, 256>>>(wv, wHi + 2 * CD, wLo + 2 * CD, CD / 4);
    cvt_kernel<<<4 * CD / 4 / 256, 256>>>(conv1_w, c1wHi, c1wLo, 4 * CD / 4);
    cvt_kernel<<<4 * CD / 4 / 256, 256>>>(conv2_w, c2wHi, c2wLo, 4 * CD / 4);
    bias_gather<<<3, 1024>>>(bq, bk, bv, bqkv);

    // 1) QKV LayerNorms -> hi/lo planes
    dim3 lng(DD / 32, BB);
    ln3_kernel<<<lng, 256>>>(x1, 3, lnq_w, lnq_b, lnk_w, lnk_b, lnv_w, lnv_b, lnHi, lnLo);

    // 2) fused QKV linears (z = 0/1/2)
    dim3 gqkv(8, 32, 3);
    kQKV<<<gqkv, 256, SM_BT128>>>(lnHi, lnLo, BCD, 1024, wHi, wLo, 1, CD, 0, 1024,
                                  nullptr, qkvHi, qkvLo, 1, BCD, 0, 1024,
                                  nullptr, bqkv, 1024, 1.f, 4096, 1024, 1024);

    // 3+4) fused S = softmax_one(0.125 * Q K^T) -> attn output
    dim3 gqs(32, BB * HH);
    qk_softmax<<<gqs, 256, SM_QS>>>(qkvHi, qkvLo, qkvHi + BCD, qkvLo + BCD, attn);

    // 5) O = P V, scatter to x[b, i, h*64+e], fused residual add of x1
    dim3 gpv(1, 8, BB * HH);
    kPV<<<gpv, 256, SM_TR64>>>(attn, nullptr, 1048576, 1024,
                               qkvHi + 2 * (long)BCD, qkvLo + 2 * (long)BCD, 1, 65536, 0, 64,
                               xb, nullptr, nullptr, 16, CD, 64, 1024,
                               x1, nullptr, 0, 1.f, 1024, 64, 1024);

    // 6) FFN LayerNorm -> xl hi/lo
    ln3_kernel<<<lng, 256>>>(xb, 1, ffnln_w, ffnln_b, nullptr, nullptr, nullptr, nullptr,
                             xlHi, xlLo);

    // 7) conv1: h1 = GELU(W1 @ xl_z + b1)
    dim3 gc1(8, 32, BB);
    kC1<<<gc1, 256, SM_TR128>>>(c1wHi, c1wLo, 0, 1024, xlHi, xlLo, 1, CD, 0, 1024,
                                nullptr, h1Hi, h1Lo, 1, (long)4096 * 1024, 0, 1024,
                                nullptr, conv1_b, 0, 1.f, 4096, 1024, 1024);

    // 8) conv2 + residual: out = x + (W2 @ h1_z + b2)
    dim3 gc2(8, 8, BB);
    kC2<<<gc2, 256, SM_TR128>>>(c2wHi, c2wLo, 0, 4096, h1Hi, h1Lo, 1, (long)4096 * 1024, 0, 1024,
                                outx, nullptr, nullptr, 1, CD, 0, 1024,
                                xb, conv2_b, 0, 1.f, 1024, 1024, 4096);
}

// round 9
// speedup vs baseline: 1.0022x; 1.0022x over previous
#include <cuda_runtime.h>
#include <cuda_bf16.h>
#include <math.h>
#include <stdint.h>

#define BB   4
#define CC   1024
#define DD   1024
#define HH   16
#define CD   (CC*DD)          // 1048576
#define BCD  (BB*CD)          // 4194304
#define H1SZ (BB*4096*1024)   // 16777216

// ---------------- scratch (static __device__ arrays; no runtime alloc) ---------------
__device__ __nv_bfloat16 g_ln_hi[3*BCD],  g_ln_lo[3*BCD];
__device__ __nv_bfloat16 g_qkv_hi[3*BCD], g_qkv_lo[3*BCD];
__device__ __nv_bfloat16 g_w_hi[3*CD],    g_w_lo[3*CD];
__device__ __nv_bfloat16 g_c1w_hi[4*CD],  g_c1w_lo[4*CD];
__device__ __nv_bfloat16 g_c2w_hi[4*CD],  g_c2w_lo[4*CD];
__device__ __nv_bfloat16 g_xl_hi[BCD],    g_xl_lo[BCD];
__device__ __nv_bfloat16 g_h1_hi[H1SZ],   g_h1_lo[H1SZ];
__device__ float g_x[BCD];
__device__ float g_bqkv[3*1024];

// =====================================================================================
// helpers
// =====================================================================================
__device__ __forceinline__ uint32_t smem_u32(const void* p) {
    uint32_t a;
    asm("{ .reg .u64 t; cvta.to.shared.u64 t, %1; cvt.u32.u64 %0, t; }" : "=r"(a) : "l"(p));
    return a;
}
__device__ __forceinline__ void cpa16(uint32_t s, const void* g) {
    asm volatile("cp.async.cg.shared.global [%0], [%1], 16;" :: "r"(s), "l"(g));
}
__device__ __forceinline__ void ldsm4(uint32_t addr, uint32_t& r0, uint32_t& r1,
                                      uint32_t& r2, uint32_t& r3) {
    asm volatile("ldmatrix.sync.aligned.m8n8.x4.shared.b16 {%0,%1,%2,%3}, [%4];"
                 : "=r"(r0), "=r"(r1), "=r"(r2), "=r"(r3) : "r"(addr));
}
__device__ __forceinline__ void ldsm4t(uint32_t addr, uint32_t& r0, uint32_t& r1,
                                       uint32_t& r2, uint32_t& r3) {
    asm volatile("ldmatrix.sync.aligned.m8n8.x4.trans.shared.b16 {%0,%1,%2,%3}, [%4];"
                 : "=r"(r0), "=r"(r1), "=r"(r2), "=r"(r3) : "r"(addr));
}
__device__ __forceinline__ void mma16816(float* c, const uint32_t* a, const uint32_t* b) {
    asm volatile(
        "mma.sync.aligned.m16n8k16.row.col.f32.bf16.bf16.f32 "
        "{%0,%1,%2,%3}, {%4,%5,%6,%7}, {%8,%9}, {%0,%1,%2,%3};"
        : "+f"(c[0]), "+f"(c[1]), "+f"(c[2]), "+f"(c[3])
        : "r"(a[0]), "r"(a[1]), "r"(a[2]), "r"(a[3]), "r"(b[0]), "r"(b[1]));
}
__device__ __forceinline__ void split1(float v, __nv_bfloat16& h, __nv_bfloat16& l) {
    h = __float2bfloat16(v);
    l = __float2bfloat16(v - __bfloat162float(h));
}

// =====================================================================================
// Tensor-core GEMM: block 128x64, 4 warps (warp tile 64x32), BK=32, 2-stage cp.async
// with RACE-FREE ordering (sync BEFORE next-stage issue), 3 CTAs/SM.
// bf16 hi/lo 3-MMA (fp32-class accuracy).
//   A: bf16 hi/lo (M,K) K-contig (or fp32 if ACONV, converted in-kernel)
//   B: BTRANS=0 -> (N,K) K-contig; BTRANS=1 -> (K,N) N-contig (ldsm .trans)
// =====================================================================================
template<bool BTRANS, bool ACONV, bool BIAS_M, bool BIAS_N,
         bool GELUF, bool ADDF, bool SCALEF, bool OSPLIT>
__global__ void __launch_bounds__(128, 3)
tc2_gemm(const void* Ahv, const __nv_bfloat16* Alo, long strideA, int lda,
         const __nv_bfloat16* Bhi, const __nv_bfloat16* Blo,
         int bDiv, long bHi, long bLo, int ldb,
         float* Cf, __nv_bfloat16* Chi, __nv_bfloat16* Clo,
         int cDiv, long cHi, long cLo, int ldc,
         const float* Add, const float* bias, int biasZ,
         float alpha, int M, int N, int K)
{
    constexpr int BN  = 64;
    constexpr int BK  = 32;
    constexpr int SKA = 40;
    constexpr int SN  = BN + 8;                    // 72
    constexpr int ASZ = 128 * SKA;                 // 5120 elems per A plane
    constexpr int BSZ = BTRANS ? (BK * SN) : (BN * SKA);
    constexpr int STAGE = 2 * ASZ + 2 * BSZ;
    constexpr int MF = 4;                          // warp tile 64x32
    constexpr int NF = 4;

    extern __shared__ __nv_bfloat16 sm[];

    const int tid = threadIdx.x, wid = tid >> 5, lid = tid & 31;
    const int wm = wid >> 1, wn = wid & 1;
    const int z = blockIdx.z;
    const int row0 = blockIdx.y * 128, col0 = blockIdx.x * BN;

    const __nv_bfloat16* Ahi = ACONV ? nullptr : ((const __nv_bfloat16*)Ahv + (long)z * strideA);
    const __nv_bfloat16* Alz = ACONV ? nullptr : (Alo + (long)z * strideA);
    const float* Af = ACONV ? ((const float*)Ahv + (long)z * strideA) : nullptr;
    Bhi += (long)(z / bDiv) * bHi + (long)(z % bDiv) * bLo;
    Blo += (long)(z / bDiv) * bHi + (long)(z % bDiv) * bLo;
    const long coff = (long)(z / cDiv) * cHi + (long)(z % cDiv) * cLo;
    if (BIAS_N || BIAS_M) bias += (long)z * biasZ;

    const uint32_t smBase = smem_u32(sm);
    const int nIt = K / BK;

    float acc[MF][NF][4];
#pragma unroll
    for (int i = 0; i < MF; i++)
#pragma unroll
        for (int j = 0; j < NF; j++)
#pragma unroll
            for (int r = 0; r < 4; r++) acc[i][j][r] = 0.f;

    float4 av[8];  // ACONV staging

    auto issueTile = [&](int it, int st) {
        const int k0 = it * BK;
        const uint32_t sbase = smBase + (uint32_t)(st * STAGE) * 2;
        if (!ACONV) {
#pragma unroll
            for (int pl = 0; pl < 2; pl++) {
                const __nv_bfloat16* Ag = pl ? Alz : Ahi;
                const uint32_t sd = sbase + (uint32_t)(pl * ASZ) * 2;
#pragma unroll
                for (int i = 0; i < 4; i++) {
                    int idx = tid + (i << 7);
                    int r = idx >> 2, c8 = (idx & 3) << 3;
                    cpa16(sd + (uint32_t)(r * SKA + c8) * 2,
                          Ag + (long)(row0 + r) * lda + k0 + c8);
                }
            }
        }
        if (BTRANS) {
#pragma unroll
            for (int pl = 0; pl < 2; pl++) {
                const __nv_bfloat16* Bg = pl ? Blo : Bhi;
                const uint32_t sd = sbase + (uint32_t)(2 * ASZ + pl * BSZ) * 2;
#pragma unroll
                for (int i = 0; i < 2; i++) {
                    int idx = tid + (i << 7);
                    int k = idx >> 3, c8 = (idx & 7) << 3;
                    cpa16(sd + (uint32_t)(k * SN + c8) * 2,
                          Bg + (long)(k0 + k) * ldb + col0 + c8);
                }
            }
        } else {
#pragma unroll
            for (int pl = 0; pl < 2; pl++) {
                const __nv_bfloat16* Bg = pl ? Blo : Bhi;
                const uint32_t sd = sbase + (uint32_t)(2 * ASZ + pl * BSZ) * 2;
#pragma unroll
                for (int i = 0; i < 2; i++) {
                    int idx = tid + (i << 7);
                    int r = idx >> 2, c8 = (idx & 3) << 3;
                    cpa16(sd + (uint32_t)(r * SKA + c8) * 2,
                          Bg + (long)(col0 + r) * ldb + k0 + c8);
                }
            }
        }
    };
    auto ldgA = [&](int it) {
        const int k0 = it * BK;
#pragma unroll
        for (int i = 0; i < 8; i++) {
            int idx = tid + (i << 7);
            int r = idx >> 3, c4 = (idx & 7) << 2;
            av[i] = *(const float4*)(Af + (long)(row0 + r) * lda + k0 + c4);
        }
    };
    auto stsA = [&](int st) {
        __nv_bfloat16* sAhi = sm + st * STAGE;
        __nv_bfloat16* sAlo = sAhi + ASZ;
#pragma unroll
        for (int i = 0; i < 8; i++) {
            int idx = tid + (i << 7);
            int r = idx >> 3, c4 = (idx & 7) << 2;
            __nv_bfloat16 h[4], l[4];
            split1(av[i].x, h[0], l[0]); split1(av[i].y, h[1], l[1]);
            split1(av[i].z, h[2], l[2]); split1(av[i].w, h[3], l[3]);
            *(uint2*)(sAhi + r * SKA + c4) = *(uint2*)h;
            *(uint2*)(sAlo + r * SKA + c4) = *(uint2*)l;
        }
    };

    // prologue: stage 0 (no readers yet -> safe before any sync)
    if (ACONV) { ldgA(0); stsA(0); }
    issueTile(0, 0);
    asm volatile("cp.async.commit_group;");

    for (int it = 0; it < nIt; it++) {
        const int s = it & 1;
        // complete stage s loads; barrier ALSO retires all readers of stage s^1
        asm volatile("cp.async.wait_group 0;");
        __syncthreads();
        // only now is it safe to overwrite stage s^1
        if (it + 1 < nIt) {
            if (ACONV) ldgA(it + 1);
            issueTile(it + 1, s ^ 1);
            asm volatile("cp.async.commit_group;");
        }

        const uint32_t base = smBase + (uint32_t)(s * STAGE) * 2;
        const uint32_t aHiB = base, aLoB = base + ASZ * 2;
        const uint32_t bHiB = base + 2 * ASZ * 2, bLoB = bHiB + BSZ * 2;

#pragma unroll
        for (int ks = 0; ks < 2; ks++) {
            uint32_t ah[MF][4], al[MF][4], bh[NF][2], bl[NF][2];
#pragma unroll
            for (int mf = 0; mf < MF; mf++) {
                uint32_t off = (uint32_t)((wm * 64 + mf * 16 + (lid & 15)) * SKA
                                          + ks * 16 + (lid >> 4) * 8) * 2;
                ldsm4(aHiB + off, ah[mf][0], ah[mf][1], ah[mf][2], ah[mf][3]);
                ldsm4(aLoB + off, al[mf][0], al[mf][1], al[mf][2], al[mf][3]);
            }
            if (BTRANS) {
#pragma unroll
                for (int p = 0; p < NF / 2; p++) {
                    uint32_t off = (uint32_t)((ks * 16 + (lid & 15)) * SN
                                              + wn * 32 + p * 16 + (lid >> 4) * 8) * 2;
                    ldsm4t(bHiB + off, bh[2*p][0], bh[2*p][1], bh[2*p+1][0], bh[2*p+1][1]);
                    ldsm4t(bLoB + off, bl[2*p][0], bl[2*p][1], bl[2*p+1][0], bl[2*p+1][1]);
                }
            } else {
#pragma unroll
                for (int p = 0; p < NF / 2; p++) {
                    uint32_t off = (uint32_t)((wn * 32 + p * 16 + (lid & 7) + (lid >> 4) * 8) * SKA
                                              + ks * 16 + ((lid >> 3) & 1) * 8) * 2;
                    ldsm4(bHiB + off, bh[2*p][0], bh[2*p][1], bh[2*p+1][0], bh[2*p+1][1]);
                    ldsm4(bLoB + off, bl[2*p][0], bl[2*p][1], bl[2*p+1][0], bl[2*p+1][1]);
                }
            }
#pragma unroll
            for (int mf = 0; mf < MF; mf++)
#pragma unroll
                for (int nf = 0; nf < NF; nf++)
                    mma16816(acc[mf][nf], ah[mf], bh[nf]);
#pragma unroll
            for (int mf = 0; mf < MF; mf++)
#pragma unroll
                for (int nf = 0; nf < NF; nf++)
                    mma16816(acc[mf][nf], ah[mf], bl[nf]);
#pragma unroll
            for (int mf = 0; mf < MF; mf++)
#pragma unroll
                for (int nf = 0; nf < NF; nf++)
                    mma16816(acc[mf][nf], al[mf], bh[nf]);
        }
        // write next stage's A (stage s^1): its old readers retired at this
        // iteration's barrier; its new readers wait for next iteration's barrier
        if (ACONV && it + 1 < nIt) stsA(s ^ 1);
    }

    // ---- epilogue ----
    float* Cp = OSPLIT ? nullptr : (Cf + coff);
    __nv_bfloat16* ChP = OSPLIT ? (Chi + coff) : nullptr;
    __nv_bfloat16* ClP = OSPLIT ? (Clo + coff) : nullptr;
    const float* Ap2 = ADDF ? (Add + coff) : nullptr;
    const int rBase = row0 + wm * 64 + (lid >> 2);
    const int cBase = col0 + wn * 32 + (lid & 3) * 2;
#pragma unroll
    for (int mf = 0; mf < MF; mf++) {
#pragma unroll
        for (int half = 0; half < 2; half++) {
            const int gr = rBase + mf * 16 + half * 8;
            const float bm = BIAS_M ? bias[gr] : 0.f;
#pragma unroll
            for (int nf = 0; nf < NF; nf++) {
                const int gc = cBase + nf * 8;
                float v0 = acc[mf][nf][half * 2 + 0];
                float v1 = acc[mf][nf][half * 2 + 1];
                if (SCALEF) { v0 *= alpha; v1 *= alpha; }
                if (BIAS_M) { v0 += bm; v1 += bm; }
                if (BIAS_N) { v0 += bias[gc]; v1 += bias[gc + 1]; }
                if (GELUF) {
                    v0 = 0.5f * v0 * (1.0f + erff(v0 * 0.70710678118654752f));
                    v1 = 0.5f * v1 * (1.0f + erff(v1 * 0.70710678118654752f));
                }
                long off = (long)gr * ldc + gc;
                if (ADDF) { v0 += Ap2[off]; v1 += Ap2[off + 1]; }
                if (OSPLIT) {
                    __nv_bfloat16 h0, l0, h1, l1;
                    split1(v0, h0, l0); split1(v1, h1, l1);
                    __nv_bfloat16 hp[2] = {h0, h1}, lp[2] = {l0, l1};
                    *(uint32_t*)(ChP + off) = *(uint32_t*)hp;
                    *(uint32_t*)(ClP + off) = *(uint32_t*)lp;
                } else {
                    *(float2*)(Cp + off) = make_float2(v0, v1);
                }
            }
        }
    }
}

// =====================================================================================
// Fused QK^T * 0.125 + softmax-one -> attn out (R6 known-good version).
// =====================================================================================
__global__ void __launch_bounds__(256, 1)
qk_softmax(const __nv_bfloat16* __restrict__ qHi, const __nv_bfloat16* __restrict__ qLo,
           const __nv_bfloat16* __restrict__ kHi, const __nv_bfloat16* __restrict__ kLo,
           float* __restrict__ attn)
{
    constexpr int SK = 72;
    constexpr int QPL = 32 * SK;
    constexpr int KPL = 128 * SK;
    extern __shared__ __nv_bfloat16 sm[];
    float* redA = (float*)(sm + 2 * QPL + 4 * KPL);
    float* redB = redA + 32 * 9;

    const int tid = threadIdx.x, wid = tid >> 5, lid = tid & 31;
    const int z = blockIdx.y;
    const int row0 = blockIdx.x * 32;
    const __nv_bfloat16* Qh = qHi + (long)z * 65536;
    const __nv_bfloat16* Ql = qLo + (long)z * 65536;
    const __nv_bfloat16* Kh = kHi + (long)z * 65536;
    const __nv_bfloat16* Kl = kLo + (long)z * 65536;
    attn += (long)z * 1048576;

    const uint32_t smBase = smem_u32(sm);

    {
        int r = tid >> 3, c8 = (tid & 7) << 3;
        cpa16(smBase + (uint32_t)(r * SK + c8) * 2,        Qh + (long)(row0 + r) * 64 + c8);
        cpa16(smBase + (uint32_t)(QPL + r * SK + c8) * 2,  Ql + (long)(row0 + r) * 64 + c8);
    }
    auto issueK = [&](int ch, int st) {
        const uint32_t sb = smBase + (uint32_t)(2 * QPL + st * 2 * KPL) * 2;
#pragma unroll
        for (int pl = 0; pl < 2; pl++) {
            const __nv_bfloat16* Kg = pl ? Kl : Kh;
            const uint32_t sd = sb + (uint32_t)(pl * KPL) * 2;
#pragma unroll
            for (int i = 0; i < 4; i++) {
                int idx = tid + (i << 8);
                int r = idx >> 3, c8 = (idx & 7) << 3;
                cpa16(sd + (uint32_t)(r * SK + c8) * 2,
                      Kg + (long)(ch * 128 + r) * 64 + c8);
            }
        }
    };
    issueK(0, 0);
    asm volatile("cp.async.commit_group;");

    float acc[2][8][2][4];
#pragma unroll
    for (int mf = 0; mf < 2; mf++)
#pragma unroll
        for (int ch = 0; ch < 8; ch++)
#pragma unroll
            for (int nf = 0; nf < 2; nf++)
#pragma unroll
                for (int r = 0; r < 4; r++) acc[mf][ch][nf][r] = 0.f;

    uint32_t aH[4][2][4], aL[4][2][4];

    for (int ch = 0; ch < 8; ch++) {
        asm volatile("cp.async.wait_group 0;");
        __syncthreads();
        if (ch + 1 < 8) {
            issueK(ch + 1, (ch + 1) & 1);
            asm volatile("cp.async.commit_group;");
        }
        if (ch == 0) {
#pragma unroll
            for (int ks = 0; ks < 4; ks++)
#pragma unroll
                for (int mf = 0; mf < 2; mf++) {
                    uint32_t off = (uint32_t)((mf * 16 + (lid & 15)) * SK
                                              + ks * 16 + (lid >> 4) * 8) * 2;
                    ldsm4(smBase + off,           aH[ks][mf][0], aH[ks][mf][1],
                                                  aH[ks][mf][2], aH[ks][mf][3]);
                    ldsm4(smBase + QPL * 2 + off, aL[ks][mf][0], aL[ks][mf][1],
                                                  aL[ks][mf][2], aL[ks][mf][3]);
                }
        }
        const int st = ch & 1;
        const uint32_t kHiB = smBase + (uint32_t)(2 * QPL + st * 2 * KPL) * 2;
        const uint32_t kLoB = kHiB + (uint32_t)KPL * 2;
        const int wn = wid;
#pragma unroll
        for (int ks = 0; ks < 4; ks++) {
            uint32_t bh[2][2], bl[2][2];
            uint32_t off = (uint32_t)((wn * 16 + (lid & 7) + (lid >> 4) * 8) * SK
                                      + ks * 16 + ((lid >> 3) & 1) * 8) * 2;
            ldsm4(kHiB + off, bh[0][0], bh[0][1], bh[1][0], bh[1][1]);
            ldsm4(kLoB + off, bl[0][0], bl[0][1], bl[1][0], bl[1][1]);
#pragma unroll
            for (int mf = 0; mf < 2; mf++)
#pragma unroll
                for (int nf = 0; nf < 2; nf++) {
                    mma16816(acc[mf][ch][nf], aH[ks][mf], bh[nf]);
                    mma16816(acc[mf][ch][nf], aH[ks][mf], bl[nf]);
                    mma16816(acc[mf][ch][nf], aL[ks][mf], bh[nf]);
                }
        }
    }

    const int rq = lid >> 2, cq = lid & 3;
    const int wn = wid;
#pragma unroll
    for (int mf = 0; mf < 2; mf++)
#pragma unroll
        for (int ch = 0; ch < 8; ch++)
#pragma unroll
            for (int nf = 0; nf < 2; nf++)
#pragma unroll
                for (int r = 0; r < 4; r++) acc[mf][ch][nf][r] *= 0.125f;

    float mx[2][2];
#pragma unroll
    for (int mf = 0; mf < 2; mf++)
#pragma unroll
        for (int half = 0; half < 2; half++) {
            float m = -1e30f;
#pragma unroll
            for (int ch = 0; ch < 8; ch++)
#pragma unroll
                for (int nf = 0; nf < 2; nf++)
                    m = fmaxf(m, fmaxf(acc[mf][ch][nf][half*2], acc[mf][ch][nf][half*2+1]));
            m = fmaxf(m, __shfl_xor_sync(0xffffffffu, m, 1));
            m = fmaxf(m, __shfl_xor_sync(0xffffffffu, m, 2));
            mx[mf][half] = m;
        }
    if (cq == 0) {
#pragma unroll
        for (int mf = 0; mf < 2; mf++)
#pragma unroll
            for (int half = 0; half < 2; half++)
                redA[(mf * 16 + half * 8 + rq) * 9 + wid] = mx[mf][half];
    }
    __syncthreads();
#pragma unroll
    for (int mf = 0; mf < 2; mf++)
#pragma unroll
        for (int half = 0; half < 2; half++) {
            float m = -1e30f;
            const float* rr = redA + (mf * 16 + half * 8 + rq) * 9;
#pragma unroll
            for (int w = 0; w < 8; w++) m = fmaxf(m, rr[w]);
            mx[mf][half] = m;
        }

    float sum[2][2] = {{0.f, 0.f}, {0.f, 0.f}};
#pragma unroll
    for (int mf = 0; mf < 2; mf++)
#pragma unroll
        for (int half = 0; half < 2; half++) {
            const float m = mx[mf][half];
            float s = 0.f;
#pragma unroll
            for (int ch = 0; ch < 8; ch++)
#pragma unroll
                for (int nf = 0; nf < 2; nf++) {
                    float e0 = __expf(acc[mf][ch][nf][half*2]     - m);
                    float e1 = __expf(acc[mf][ch][nf][half*2 + 1] - m);
                    acc[mf][ch][nf][half*2]     = e0;
                    acc[mf][ch][nf][half*2 + 1] = e1;
                    s += e0 + e1;
                }
            s += __shfl_xor_sync(0xffffffffu, s, 1);
            s += __shfl_xor_sync(0xffffffffu, s, 2);
            sum[mf][half] = s;
        }
    if (cq == 0) {
#pragma unroll
        for (int mf = 0; mf < 2; mf++)
#pragma unroll
            for (int half = 0; half < 2; half++)
                redB[(mf * 16 + half * 8 + rq) * 9 + wid] = sum[mf][half];
    }
    __syncthreads();
#pragma unroll
    for (int mf = 0; mf < 2; mf++)
#pragma unroll
        for (int half = 0; half < 2; half++) {
            float s = 0.f;
            const float* rr = redB + (mf * 16 + half * 8 + rq) * 9;
#pragma unroll
            for (int w = 0; w < 8; w++) s += rr[w];
            sum[mf][half] = 1.0f / (1.0f + s);
        }

#pragma unroll
    for (int mf = 0; mf < 2; mf++)
#pragma unroll
        for (int half = 0; half < 2; half++) {
            const int gr = row0 + mf * 16 + half * 8 + rq;
            const float inv = sum[mf][half];
#pragma unroll
            for (int ch = 0; ch < 8; ch++)
#pragma unroll
                for (int nf = 0; nf < 2; nf++) {
                    const int gc = ch * 128 + wn * 16 + nf * 8 + cq * 2;
                    *(float2*)(attn + (long)gr * 1024 + gc) =
                        make_float2(acc[mf][ch][nf][half*2] * inv,
                                    acc[mf][ch][nf][half*2+1] * inv);
                }
        }
}

// =====================================================================================
__global__ void cvt_kernel(const float* __restrict__ s, __nv_bfloat16* __restrict__ hi,
                           __nv_bfloat16* __restrict__ lo, int n4)
{
    int i = blockIdx.x * 256 + threadIdx.x;
    if (i >= n4) return;
    float4 v = ((const float4*)s)[i];
    __nv_bfloat16 h[4], l[4];
    split1(v.x, h[0], l[0]); split1(v.y, h[1], l[1]);
    split1(v.z, h[2], l[2]); split1(v.w, h[3], l[3]);
    ((uint2*)hi)[i] = *(uint2*)h;
    ((uint2*)lo)[i] = *(uint2*)l;
}

__global__ void bias_gather(const float* a, const float* b, const float* c, float* o)
{
    const float* src[3] = {a, b, c};
    o[blockIdx.x * 1024 + threadIdx.x] = src[blockIdx.x][threadIdx.x];
}

// =====================================================================================
__global__ void ln3_kernel(const float* __restrict__ x, int nOut,
    const float* __restrict__ w0, const float* __restrict__ b0,
    const float* __restrict__ w1, const float* __restrict__ b1,
    const float* __restrict__ w2, const float* __restrict__ b2,
    __nv_bfloat16* __restrict__ oHi, __nv_bfloat16* __restrict__ oLo)
{
    const int dx   = threadIdx.x & 31;
    const int lane = threadIdx.x >> 5;
    const int d    = blockIdx.x * 32 + dx;
    const long base = (long)blockIdx.y * CD + d;

    float s = 0.f, ss = 0.f;
    for (int c = lane; c < CC; c += 8) {
        float v = x[base + (long)c * DD];
        s += v; ss += v * v;
    }
    __shared__ float sS[8][33], sQ[8][33];
    sS[lane][dx] = s; sQ[lane][dx] = ss;
    __syncthreads();
    if (lane == 0) {
        float ts = 0.f, tq = 0.f;
        #pragma unroll
        for (int i = 0; i < 8; i++) { ts += sS[i][dx]; tq += sQ[i][dx]; }
        float mean = ts * (1.0f / CC);
        float var  = tq * (1.0f / CC) - mean * mean;
        sS[0][dx] = mean;
        sQ[0][dx] = rsqrtf(var + 1e-6f);
    }
    __syncthreads();
    const float mean = sS[0][dx];
    const float rstd = sQ[0][dx];
    const float* W[3] = {w0, w1, w2};
    const float* Bv[3] = {b0, b1, b2};
    for (int c = lane; c < CC; c += 8) {
        long idx = base + (long)c * DD;
        float xn = (x[idx] - mean) * rstd;
        for (int p = 0; p < nOut; p++) {
            float v = W[p][c] * xn + Bv[p][c];
            __nv_bfloat16 h, l;
            split1(v, h, l);
            oHi[(long)p * BCD + idx] = h;
            oLo[(long)p * BCD + idx] = l;
        }
    }
}

// =====================================================================================
extern "C" void kernel_launch(void* const* d_in, const int* in_sizes, int n_in,
                              void* d_out, int out_size)
{
    const float* x1      = (const float*)d_in[0];
    const float* lnq_w   = (const float*)d_in[1];
    const float* lnq_b   = (const float*)d_in[2];
    const float* lnk_w   = (const float*)d_in[3];
    const float* lnk_b   = (const float*)d_in[4];
    const float* lnv_w   = (const float*)d_in[5];
    const float* lnv_b   = (const float*)d_in[6];
    const float* wq      = (const float*)d_in[7];
    const float* bq      = (const float*)d_in[8];
    const float* wk      = (const float*)d_in[9];
    const float* bk      = (const float*)d_in[10];
    const float* wv      = (const float*)d_in[11];
    const float* bv      = (const float*)d_in[12];
    const float* ffnln_w = (const float*)d_in[13];
    const float* ffnln_b = (const float*)d_in[14];
    const float* conv1_w = (const float*)d_in[15];
    const float* conv1_b = (const float*)d_in[16];
    const float* conv2_w = (const float*)d_in[17];
    const float* conv2_b = (const float*)d_in[18];

    __nv_bfloat16 *lnHi, *lnLo, *qkvHi, *qkvLo, *wHi, *wLo;
    __nv_bfloat16 *c1wHi, *c1wLo, *c2wHi, *c2wLo, *xlHi, *xlLo, *h1Hi, *h1Lo;
    float *xb, *bqkv;
    cudaGetSymbolAddress((void**)&lnHi,  g_ln_hi);   cudaGetSymbolAddress((void**)&lnLo,  g_ln_lo);
    cudaGetSymbolAddress((void**)&qkvHi, g_qkv_hi);  cudaGetSymbolAddress((void**)&qkvLo, g_qkv_lo);
    cudaGetSymbolAddress((void**)&wHi,   g_w_hi);    cudaGetSymbolAddress((void**)&wLo,   g_w_lo);
    cudaGetSymbolAddress((void**)&c1wHi, g_c1w_hi);  cudaGetSymbolAddress((void**)&c1wLo, g_c1w_lo);
    cudaGetSymbolAddress((void**)&c2wHi, g_c2w_hi);  cudaGetSymbolAddress((void**)&c2wLo, g_c2w_lo);
    cudaGetSymbolAddress((void**)&xlHi,  g_xl_hi);   cudaGetSymbolAddress((void**)&xlLo,  g_xl_lo);
    cudaGetSymbolAddress((void**)&h1Hi,  g_h1_hi);   cudaGetSymbolAddress((void**)&h1Lo,  g_h1_lo);
    cudaGetSymbolAddress((void**)&xb,    g_x);
    cudaGetSymbolAddress((void**)&bqkv,  g_bqkv);

    float* outx = (float*)d_out;
    float* attn = outx + (long)BCD;

    auto kQKV = tc2_gemm<false, false, false, true,  false, false, false, true >;
    auto kPV  = tc2_gemm<true,  true,  false, false, false, true,  false, false>;
    auto kC1  = tc2_gemm<true,  false, true,  false, true,  false, false, true >;
    auto kC2  = tc2_gemm<true,  false, true,  false, false, true,  false, false>;
    const int SM_KB = 2 * (2 * 128 * 40 + 2 * 64 * 40) * 2;   // 61440
    const int SM_TR = 2 * (2 * 128 * 40 + 2 * 32 * 72) * 2;   // 59392
    const int SM_QS = (2 * 32 * 72 + 4 * 128 * 72) * 2 + 2 * 32 * 9 * 4;  // 85248
    cudaFuncSetAttribute(kQKV, cudaFuncAttributeMaxDynamicSharedMemorySize, SM_KB);
    cudaFuncSetAttribute(kPV,  cudaFuncAttributeMaxDynamicSharedMemorySize, SM_TR);
    cudaFuncSetAttribute(kC1,  cudaFuncAttributeMaxDynamicSharedMemorySize, SM_TR);
    cudaFuncSetAttribute(kC2,  cudaFuncAttributeMaxDynamicSharedMemorySize, SM_TR);
    cudaFuncSetAttribute(qk_softmax, cudaFuncAttributeMaxDynamicSharedMemorySize, SM_QS);

    // 0) pre-split weights + gather qkv biases
    cvt_kernel<<<CD / 4 / 256, 256>>>(wq, wHi,          wLo,          CD / 4);
    cvt_kernel<<<CD / 4 / 256, 256>>>(wk, wHi + CD,     wLo + CD,     CD / 4);
    cvt_kernel<<<CD / 4 / 256, 256>>>(wv, wHi + 2 * CD, wLo + 2 * CD, CD / 4);
    cvt_kernel<<<4 * CD / 4 / 256, 256>>>(conv1_w, c1wHi, c1wLo, 4 * CD / 4);
    cvt_kernel<<<4 * CD / 4 / 256, 256>>>(conv2_w, c2wHi, c2wLo, 4 * CD / 4);
    bias_gather<<<3, 1024>>>(bq, bk, bv, bqkv);

    // 1) QKV LayerNorms -> hi/lo planes
    dim3 lng(DD / 32, BB);
    ln3_kernel<<<lng, 256>>>(x1, 3, lnq_w, lnq_b, lnk_w, lnk_b, lnv_w, lnv_b, lnHi, lnLo);

    // 2) fused QKV linears (z = 0/1/2)
    dim3 gqkv(16, 32, 3);
    kQKV<<<gqkv, 128, SM_KB>>>(lnHi, lnLo, BCD, 1024, wHi, wLo, 1, CD, 0, 1024,
                               nullptr, qkvHi, qkvLo, 1, BCD, 0, 1024,
                               nullptr, bqkv, 1024, 1.f, 4096, 1024, 1024);

    // 3+4) fused S = softmax_one(0.125 * Q K^T) -> attn output
    dim3 gqs(32, BB * HH);
    qk_softmax<<<gqs, 256, SM_QS>>>(qkvHi, qkvLo, qkvHi + BCD, qkvLo + BCD, attn);

    // 5) O = P V, scatter to x[b, i, h*64+e], fused residual add of x1
    dim3 gpv(1, 8, BB * HH);
    kPV<<<gpv, 128, SM_TR>>>(attn, nullptr, 1048576, 1024,
                             qkvHi + 2 * (long)BCD, qkvLo + 2 * (long)BCD, 1, 65536, 0, 64,
                             xb, nullptr, nullptr, 16, CD, 64, 1024,
                             x1, nullptr, 0, 1.f, 1024, 64, 1024);

    // 6) FFN LayerNorm -> xl hi/lo
    ln3_kernel<<<lng, 256>>>(xb, 1, ffnln_w, ffnln_b, nullptr, nullptr, nullptr, nullptr,
                             xlHi, xlLo);

    // 7) conv1: h1 = GELU(W1 @ xl_z + b1)
    dim3 gc1(16, 32, BB);
    kC1<<<gc1, 128, SM_TR>>>(c1wHi, c1wLo, 0, 1024, xlHi, xlLo, 1, CD, 0, 1024,
                             nullptr, h1Hi, h1Lo, 1, (long)4096 * 1024, 0, 1024,
                             nullptr, conv1_b, 0, 1.f, 4096, 1024, 1024);

    // 8) conv2 + residual: out = x + (W2 @ h1_z + b2)
    dim3 gc2(16, 8, BB);
    kC2<<<gc2, 128, SM_TR>>>(c2wHi, c2wLo, 0, 4096, h1Hi, h1Lo, 1, (long)4096 * 1024, 0, 1024,
                             outx, nullptr, nullptr, 1, CD, 0, 1024,
                             xb, conv2_b, 0, 1.f, 1024, 1024, 4096);
}

// round 10
// speedup vs baseline: 1.1929x; 1.1904x over previous
#include <cuda_runtime.h>
#include <cuda_fp16.h>
#include <math.h>
#include <stdint.h>

#define BB   4
#define CC   1024
#define DD   1024
#define HH   16
#define CD   (CC*DD)          // 1048576
#define BCD  (BB*CD)          // 4194304
#define H1SZ (BB*4096*1024)   // 16777216

// ---------------- scratch (static __device__ arrays; no runtime alloc) ---------------
__device__ __half g_ln_hi[3*BCD],  g_ln_lo[3*BCD];
__device__ __half g_qkv_hi[3*BCD], g_qkv_lo[3*BCD];
__device__ __half g_w_hi[3*CD];                       // qkv weights: single plane (B role)
__device__ __half g_c1w_hi[4*CD],  g_c1w_lo[4*CD];    // A role: hi/lo
__device__ __half g_c2w_hi[4*CD],  g_c2w_lo[4*CD];    // A role: hi/lo
__device__ __half g_xl_hi[BCD],    g_xl_lo[BCD];
__device__ __half g_h1_hi[H1SZ],   g_h1_lo[H1SZ];
__device__ float g_x[BCD];
__device__ float g_bqkv[3*1024];

// =====================================================================================
// helpers
// =====================================================================================
__device__ __forceinline__ uint32_t smem_u32(const void* p) {
    uint32_t a;
    asm("{ .reg .u64 t; cvta.to.shared.u64 t, %1; cvt.u32.u64 %0, t; }" : "=r"(a) : "l"(p));
    return a;
}
__device__ __forceinline__ void cpa16(uint32_t s, const void* g) {
    asm volatile("cp.async.cg.shared.global [%0], [%1], 16;" :: "r"(s), "l"(g));
}
__device__ __forceinline__ void ldsm4(uint32_t addr, uint32_t& r0, uint32_t& r1,
                                      uint32_t& r2, uint32_t& r3) {
    asm volatile("ldmatrix.sync.aligned.m8n8.x4.shared.b16 {%0,%1,%2,%3}, [%4];"
                 : "=r"(r0), "=r"(r1), "=r"(r2), "=r"(r3) : "r"(addr));
}
__device__ __forceinline__ void ldsm4t(uint32_t addr, uint32_t& r0, uint32_t& r1,
                                       uint32_t& r2, uint32_t& r3) {
    asm volatile("ldmatrix.sync.aligned.m8n8.x4.trans.shared.b16 {%0,%1,%2,%3}, [%4];"
                 : "=r"(r0), "=r"(r1), "=r"(r2), "=r"(r3) : "r"(addr));
}
__device__ __forceinline__ void mma16816(float* c, const uint32_t* a, const uint32_t* b) {
    asm volatile(
        "mma.sync.aligned.m16n8k16.row.col.f32.f16.f16.f32 "
        "{%0,%1,%2,%3}, {%4,%5,%6,%7}, {%8,%9}, {%0,%1,%2,%3};"
        : "+f"(c[0]), "+f"(c[1]), "+f"(c[2]), "+f"(c[3])
        : "r"(a[0]), "r"(a[1]), "r"(a[2]), "r"(a[3]), "r"(b[0]), "r"(b[1]));
}
// fp32 -> fp16 hi + fp16 lo (residual); pair carries ~22 mantissa bits
__device__ __forceinline__ void split1(float v, __half& h, __half& l) {
    h = __float2half_rn(v);
    l = __float2half_rn(v - __half2float(h));
}

// =====================================================================================
// Tensor-core GEMM: block 128x64, 4 warps (warp tile 64x32), BK=32, 2-stage cp.async
// (race-free ordering), 3 CTAs/SM.
//   NMMA=2: D = (a_hi + a_lo) x b      (B single fp16 plane; ~2^-12 operand error)
//   NMMA=3: D = a_hi*b_hi + a_hi*b_lo + a_lo*b_hi   (fp32-class)
//   A: fp16 hi/lo (M,K) K-contig (or fp32 if ACONV, split in-kernel)
//   B: BTRANS=0 -> (N,K) K-contig; BTRANS=1 -> (K,N) N-contig (ldsm .trans)
// =====================================================================================
template<int NMMA, bool BTRANS, bool ACONV, bool BIAS_M, bool BIAS_N,
         bool GELUF, bool ADDF, bool SCALEF, bool OSPLIT>
__global__ void __launch_bounds__(128, 3)
tc2_gemm(const void* Ahv, const __half* Alo, long strideA, int lda,
         const __half* Bhi, const __half* Blo,
         int bDiv, long bHi, long bLo, int ldb,
         float* Cf, __half* Chi, __half* Clo,
         int cDiv, long cHi, long cLo, int ldc,
         const float* Add, const float* bias, int biasZ,
         float alpha, int M, int N, int K)
{
    constexpr int BN  = 64;
    constexpr int BK  = 32;
    constexpr int SKA = 40;
    constexpr int SN  = BN + 8;                    // 72
    constexpr int ASZ = 128 * SKA;                 // 5120 elems per A plane
    constexpr int BSZ = BTRANS ? (BK * SN) : (BN * SKA);
    constexpr int BPL = (NMMA == 3) ? 2 : 1;       // B planes
    constexpr int STAGE = 2 * ASZ + BPL * BSZ;
    constexpr int MF = 4;                          // warp tile 64x32
    constexpr int NF = 4;

    extern __shared__ __half sm[];

    const int tid = threadIdx.x, wid = tid >> 5, lid = tid & 31;
    const int wm = wid >> 1, wn = wid & 1;
    const int z = blockIdx.z;
    const int row0 = blockIdx.y * 128, col0 = blockIdx.x * BN;

    const __half* Ahi = ACONV ? nullptr : ((const __half*)Ahv + (long)z * strideA);
    const __half* Alz = ACONV ? nullptr : (Alo + (long)z * strideA);
    const float* Af = ACONV ? ((const float*)Ahv + (long)z * strideA) : nullptr;
    Bhi += (long)(z / bDiv) * bHi + (long)(z % bDiv) * bLo;
    if (NMMA == 3) Blo += (long)(z / bDiv) * bHi + (long)(z % bDiv) * bLo;
    const long coff = (long)(z / cDiv) * cHi + (long)(z % cDiv) * cLo;
    if (BIAS_N || BIAS_M) bias += (long)z * biasZ;

    const uint32_t smBase = smem_u32(sm);
    const int nIt = K / BK;

    float acc[MF][NF][4];
#pragma unroll
    for (int i = 0; i < MF; i++)
#pragma unroll
        for (int j = 0; j < NF; j++)
#pragma unroll
            for (int r = 0; r < 4; r++) acc[i][j][r] = 0.f;

    float4 av[8];  // ACONV staging

    auto issueTile = [&](int it, int st) {
        const int k0 = it * BK;
        const uint32_t sbase = smBase + (uint32_t)(st * STAGE) * 2;
        if (!ACONV) {
#pragma unroll
            for (int pl = 0; pl < 2; pl++) {
                const __half* Ag = pl ? Alz : Ahi;
                const uint32_t sd = sbase + (uint32_t)(pl * ASZ) * 2;
#pragma unroll
                for (int i = 0; i < 4; i++) {
                    int idx = tid + (i << 7);
                    int r = idx >> 2, c8 = (idx & 3) << 3;
                    cpa16(sd + (uint32_t)(r * SKA + c8) * 2,
                          Ag + (long)(row0 + r) * lda + k0 + c8);
                }
            }
        }
        if (BTRANS) {
#pragma unroll
            for (int pl = 0; pl < BPL; pl++) {
                const __half* Bg = pl ? Blo : Bhi;
                const uint32_t sd = sbase + (uint32_t)(2 * ASZ + pl * BSZ) * 2;
#pragma unroll
                for (int i = 0; i < 2; i++) {
                    int idx = tid + (i << 7);
                    int k = idx >> 3, c8 = (idx & 7) << 3;
                    cpa16(sd + (uint32_t)(k * SN + c8) * 2,
                          Bg + (long)(k0 + k) * ldb + col0 + c8);
                }
            }
        } else {
#pragma unroll
            for (int pl = 0; pl < BPL; pl++) {
                const __half* Bg = pl ? Blo : Bhi;
                const uint32_t sd = sbase + (uint32_t)(2 * ASZ + pl * BSZ) * 2;
#pragma unroll
                for (int i = 0; i < 2; i++) {
                    int idx = tid + (i << 7);
                    int r = idx >> 2, c8 = (idx & 3) << 3;
                    cpa16(sd + (uint32_t)(r * SKA + c8) * 2,
                          Bg + (long)(col0 + r) * ldb + k0 + c8);
                }
            }
        }
    };
    auto ldgA = [&](int it) {
        const int k0 = it * BK;
#pragma unroll
        for (int i = 0; i < 8; i++) {
            int idx = tid + (i << 7);
            int r = idx >> 3, c4 = (idx & 7) << 2;
            av[i] = *(const float4*)(Af + (long)(row0 + r) * lda + k0 + c4);
        }
    };
    auto stsA = [&](int st) {
        __half* sAhi = sm + st * STAGE;
        __half* sAlo = sAhi + ASZ;
#pragma unroll
        for (int i = 0; i < 8; i++) {
            int idx = tid + (i << 7);
            int r = idx >> 3, c4 = (idx & 7) << 2;
            __half h[4], l[4];
            split1(av[i].x, h[0], l[0]); split1(av[i].y, h[1], l[1]);
            split1(av[i].z, h[2], l[2]); split1(av[i].w, h[3], l[3]);
            *(uint2*)(sAhi + r * SKA + c4) = *(uint2*)h;
            *(uint2*)(sAlo + r * SKA + c4) = *(uint2*)l;
        }
    };

    if (ACONV) { ldgA(0); stsA(0); }
    issueTile(0, 0);
    asm volatile("cp.async.commit_group;");

    for (int it = 0; it < nIt; it++) {
        const int s = it & 1;
        asm volatile("cp.async.wait_group 0;");
        __syncthreads();
        if (it + 1 < nIt) {
            if (ACONV) ldgA(it + 1);
            issueTile(it + 1, s ^ 1);
            asm volatile("cp.async.commit_group;");
        }

        const uint32_t base = smBase + (uint32_t)(s * STAGE) * 2;
        const uint32_t aHiB = base, aLoB = base + ASZ * 2;
        const uint32_t bHiB = base + 2 * ASZ * 2, bLoB = bHiB + BSZ * 2;

#pragma unroll
        for (int ks = 0; ks < 2; ks++) {
            uint32_t ah[MF][4], al[MF][4], bh[NF][2], bl[NF][2];
#pragma unroll
            for (int mf = 0; mf < MF; mf++) {
                uint32_t off = (uint32_t)((wm * 64 + mf * 16 + (lid & 15)) * SKA
                                          + ks * 16 + (lid >> 4) * 8) * 2;
                ldsm4(aHiB + off, ah[mf][0], ah[mf][1], ah[mf][2], ah[mf][3]);
                ldsm4(aLoB + off, al[mf][0], al[mf][1], al[mf][2], al[mf][3]);
            }
            if (BTRANS) {
#pragma unroll
                for (int p = 0; p < NF / 2; p++) {
                    uint32_t off = (uint32_t)((ks * 16 + (lid & 15)) * SN
                                              + wn * 32 + p * 16 + (lid >> 4) * 8) * 2;
                    ldsm4t(bHiB + off, bh[2*p][0], bh[2*p][1], bh[2*p+1][0], bh[2*p+1][1]);
                    if (NMMA == 3)
                        ldsm4t(bLoB + off, bl[2*p][0], bl[2*p][1], bl[2*p+1][0], bl[2*p+1][1]);
                }
            } else {
#pragma unroll
                for (int p = 0; p < NF / 2; p++) {
                    uint32_t off = (uint32_t)((wn * 32 + p * 16 + (lid & 7) + (lid >> 4) * 8) * SKA
                                              + ks * 16 + ((lid >> 3) & 1) * 8) * 2;
                    ldsm4(bHiB + off, bh[2*p][0], bh[2*p][1], bh[2*p+1][0], bh[2*p+1][1]);
                    if (NMMA == 3)
                        ldsm4(bLoB + off, bl[2*p][0], bl[2*p][1], bl[2*p+1][0], bl[2*p+1][1]);
                }
            }
#pragma unroll
            for (int mf = 0; mf < MF; mf++)
#pragma unroll
                for (int nf = 0; nf < NF; nf++)
                    mma16816(acc[mf][nf], ah[mf], bh[nf]);
            if (NMMA == 3) {
#pragma unroll
                for (int mf = 0; mf < MF; mf++)
#pragma unroll
                    for (int nf = 0; nf < NF; nf++)
                        mma16816(acc[mf][nf], ah[mf], bl[nf]);
            }
#pragma unroll
            for (int mf = 0; mf < MF; mf++)
#pragma unroll
                for (int nf = 0; nf < NF; nf++)
                    mma16816(acc[mf][nf], al[mf], bh[nf]);
        }
        if (ACONV && it + 1 < nIt) stsA(s ^ 1);
    }

    // ---- epilogue ----
    float* Cp = OSPLIT ? nullptr : (Cf + coff);
    __half* ChP = OSPLIT ? (Chi + coff) : nullptr;
    __half* ClP = OSPLIT ? (Clo + coff) : nullptr;
    const float* Ap2 = ADDF ? (Add + coff) : nullptr;
    const int rBase = row0 + wm * 64 + (lid >> 2);
    const int cBase = col0 + wn * 32 + (lid & 3) * 2;
#pragma unroll
    for (int mf = 0; mf < MF; mf++) {
#pragma unroll
        for (int half = 0; half < 2; half++) {
            const int gr = rBase + mf * 16 + half * 8;
            const float bm = BIAS_M ? bias[gr] : 0.f;
#pragma unroll
            for (int nf = 0; nf < NF; nf++) {
                const int gc = cBase + nf * 8;
                float v0 = acc[mf][nf][half * 2 + 0];
                float v1 = acc[mf][nf][half * 2 + 1];
                if (SCALEF) { v0 *= alpha; v1 *= alpha; }
                if (BIAS_M) { v0 += bm; v1 += bm; }
                if (BIAS_N) { v0 += bias[gc]; v1 += bias[gc + 1]; }
                if (GELUF) {
                    v0 = 0.5f * v0 * (1.0f + erff(v0 * 0.70710678118654752f));
                    v1 = 0.5f * v1 * (1.0f + erff(v1 * 0.70710678118654752f));
                }
                long off = (long)gr * ldc + gc;
                if (ADDF) { v0 += Ap2[off]; v1 += Ap2[off + 1]; }
                if (OSPLIT) {
                    __half h0, l0, h1, l1;
                    split1(v0, h0, l0); split1(v1, h1, l1);
                    __half hp[2] = {h0, h1}, lp[2] = {l0, l1};
                    *(uint32_t*)(ChP + off) = *(uint32_t*)hp;
                    *(uint32_t*)(ClP + off) = *(uint32_t*)lp;
                } else {
                    *(float2*)(Cp + off) = make_float2(v0, v1);
                }
            }
        }
    }
}

// =====================================================================================
// Fused QK^T * 0.125 + softmax-one -> attn out. fp16 3-MMA (cross terms kept).
// grid (32, 64), 256 threads; Q fragments preloaded once.
// =====================================================================================
__global__ void __launch_bounds__(256, 1)
qk_softmax(const __half* __restrict__ qHi, const __half* __restrict__ qLo,
           const __half* __restrict__ kHi, const __half* __restrict__ kLo,
           float* __restrict__ attn)
{
    constexpr int SK = 72;
    constexpr int QPL = 32 * SK;
    constexpr int KPL = 128 * SK;
    extern __shared__ __half sm[];
    float* redA = (float*)(sm + 2 * QPL + 4 * KPL);
    float* redB = redA + 32 * 9;

    const int tid = threadIdx.x, wid = tid >> 5, lid = tid & 31;
    const int z = blockIdx.y;
    const int row0 = blockIdx.x * 32;
    const __half* Qh = qHi + (long)z * 65536;
    const __half* Ql = qLo + (long)z * 65536;
    const __half* Kh = kHi + (long)z * 65536;
    const __half* Kl = kLo + (long)z * 65536;
    attn += (long)z * 1048576;

    const uint32_t smBase = smem_u32(sm);

    {
        int r = tid >> 3, c8 = (tid & 7) << 3;
        cpa16(smBase + (uint32_t)(r * SK + c8) * 2,        Qh + (long)(row0 + r) * 64 + c8);
        cpa16(smBase + (uint32_t)(QPL + r * SK + c8) * 2,  Ql + (long)(row0 + r) * 64 + c8);
    }
    auto issueK = [&](int ch, int st) {
        const uint32_t sb = smBase + (uint32_t)(2 * QPL + st * 2 * KPL) * 2;
#pragma unroll
        for (int pl = 0; pl < 2; pl++) {
            const __half* Kg = pl ? Kl : Kh;
            const uint32_t sd = sb + (uint32_t)(pl * KPL) * 2;
#pragma unroll
            for (int i = 0; i < 4; i++) {
                int idx = tid + (i << 8);
                int r = idx >> 3, c8 = (idx & 7) << 3;
                cpa16(sd + (uint32_t)(r * SK + c8) * 2,
                      Kg + (long)(ch * 128 + r) * 64 + c8);
            }
        }
    };
    issueK(0, 0);
    asm volatile("cp.async.commit_group;");

    float acc[2][8][2][4];
#pragma unroll
    for (int mf = 0; mf < 2; mf++)
#pragma unroll
        for (int ch = 0; ch < 8; ch++)
#pragma unroll
            for (int nf = 0; nf < 2; nf++)
#pragma unroll
                for (int r = 0; r < 4; r++) acc[mf][ch][nf][r] = 0.f;

    uint32_t aH[4][2][4], aL[4][2][4];

    for (int ch = 0; ch < 8; ch++) {
        asm volatile("cp.async.wait_group 0;");
        __syncthreads();
        if (ch + 1 < 8) {
            issueK(ch + 1, (ch + 1) & 1);
            asm volatile("cp.async.commit_group;");
        }
        if (ch == 0) {
#pragma unroll
            for (int ks = 0; ks < 4; ks++)
#pragma unroll
                for (int mf = 0; mf < 2; mf++) {
                    uint32_t off = (uint32_t)((mf * 16 + (lid & 15)) * SK
                                              + ks * 16 + (lid >> 4) * 8) * 2;
                    ldsm4(smBase + off,           aH[ks][mf][0], aH[ks][mf][1],
                                                  aH[ks][mf][2], aH[ks][mf][3]);
                    ldsm4(smBase + QPL * 2 + off, aL[ks][mf][0], aL[ks][mf][1],
                                                  aL[ks][mf][2], aL[ks][mf][3]);
                }
        }
        const int st = ch & 1;
        const uint32_t kHiB = smBase + (uint32_t)(2 * QPL + st * 2 * KPL) * 2;
        const uint32_t kLoB = kHiB + (uint32_t)KPL * 2;
        const int wn = wid;
#pragma unroll
        for (int ks = 0; ks < 4; ks++) {
            uint32_t bh[2][2], bl[2][2];
            uint32_t off = (uint32_t)((wn * 16 + (lid & 7) + (lid >> 4) * 8) * SK
                                      + ks * 16 + ((lid >> 3) & 1) * 8) * 2;
            ldsm4(kHiB + off, bh[0][0], bh[0][1], bh[1][0], bh[1][1]);
            ldsm4(kLoB + off, bl[0][0], bl[0][1], bl[1][0], bl[1][1]);
#pragma unroll
            for (int mf = 0; mf < 2; mf++)
#pragma unroll
                for (int nf = 0; nf < 2; nf++) {
                    mma16816(acc[mf][ch][nf], aH[ks][mf], bh[nf]);
                    mma16816(acc[mf][ch][nf], aH[ks][mf], bl[nf]);
                    mma16816(acc[mf][ch][nf], aL[ks][mf], bh[nf]);
                }
        }
    }

    const int rq = lid >> 2, cq = lid & 3;
    const int wn = wid;
#pragma unroll
    for (int mf = 0; mf < 2; mf++)
#pragma unroll
        for (int ch = 0; ch < 8; ch++)
#pragma unroll
            for (int nf = 0; nf < 2; nf++)
#pragma unroll
                for (int r = 0; r < 4; r++) acc[mf][ch][nf][r] *= 0.125f;

    float mx[2][2];
#pragma unroll
    for (int mf = 0; mf < 2; mf++)
#pragma unroll
        for (int half = 0; half < 2; half++) {
            float m = -1e30f;
#pragma unroll
            for (int ch = 0; ch < 8; ch++)
#pragma unroll
                for (int nf = 0; nf < 2; nf++)
                    m = fmaxf(m, fmaxf(acc[mf][ch][nf][half*2], acc[mf][ch][nf][half*2+1]));
            m = fmaxf(m, __shfl_xor_sync(0xffffffffu, m, 1));
            m = fmaxf(m, __shfl_xor_sync(0xffffffffu, m, 2));
            mx[mf][half] = m;
        }
    if (cq == 0) {
#pragma unroll
        for (int mf = 0; mf < 2; mf++)
#pragma unroll
            for (int half = 0; half < 2; half++)
                redA[(mf * 16 + half * 8 + rq) * 9 + wid] = mx[mf][half];
    }
    __syncthreads();
#pragma unroll
    for (int mf = 0; mf < 2; mf++)
#pragma unroll
        for (int half = 0; half < 2; half++) {
            float m = -1e30f;
            const float* rr = redA + (mf * 16 + half * 8 + rq) * 9;
#pragma unroll
            for (int w = 0; w < 8; w++) m = fmaxf(m, rr[w]);
            mx[mf][half] = m;
        }

    float sum[2][2] = {{0.f, 0.f}, {0.f, 0.f}};
#pragma unroll
    for (int mf = 0; mf < 2; mf++)
#pragma unroll
        for (int half = 0; half < 2; half++) {
            const float m = mx[mf][half];
            float s = 0.f;
#pragma unroll
            for (int ch = 0; ch < 8; ch++)
#pragma unroll
                for (int nf = 0; nf < 2; nf++) {
                    float e0 = __expf(acc[mf][ch][nf][half*2]     - m);
                    float e1 = __expf(acc[mf][ch][nf][half*2 + 1] - m);
                    acc[mf][ch][nf][half*2]     = e0;
                    acc[mf][ch][nf][half*2 + 1] = e1;
                    s += e0 + e1;
                }
            s += __shfl_xor_sync(0xffffffffu, s, 1);
            s += __shfl_xor_sync(0xffffffffu, s, 2);
            sum[mf][half] = s;
        }
    if (cq == 0) {
#pragma unroll
        for (int mf = 0; mf < 2; mf++)
#pragma unroll
            for (int half = 0; half < 2; half++)
                redB[(mf * 16 + half * 8 + rq) * 9 + wid] = sum[mf][half];
    }
    __syncthreads();
#pragma unroll
    for (int mf = 0; mf < 2; mf++)
#pragma unroll
        for (int half = 0; half < 2; half++) {
            float s = 0.f;
            const float* rr = redB + (mf * 16 + half * 8 + rq) * 9;
#pragma unroll
            for (int w = 0; w < 8; w++) s += rr[w];
            sum[mf][half] = 1.0f / (1.0f + s);
        }

#pragma unroll
    for (int mf = 0; mf < 2; mf++)
#pragma unroll
        for (int half = 0; half < 2; half++) {
            const int gr = row0 + mf * 16 + half * 8 + rq;
            const float inv = sum[mf][half];
#pragma unroll
            for (int ch = 0; ch < 8; ch++)
#pragma unroll
                for (int nf = 0; nf < 2; nf++) {
                    const int gc = ch * 128 + wn * 16 + nf * 8 + cq * 2;
                    *(float2*)(attn + (long)gr * 1024 + gc) =
                        make_float2(acc[mf][ch][nf][half*2] * inv,
                                    acc[mf][ch][nf][half*2+1] * inv);
                }
        }
}

// =====================================================================================
// fp32 -> fp16 hi(/lo) converts
// =====================================================================================
__global__ void cvt_hilo(const float* __restrict__ s, __half* __restrict__ hi,
                         __half* __restrict__ lo, int n4)
{
    int i = blockIdx.x * 256 + threadIdx.x;
    if (i >= n4) return;
    float4 v = ((const float4*)s)[i];
    __half h[4], l[4];
    split1(v.x, h[0], l[0]); split1(v.y, h[1], l[1]);
    split1(v.z, h[2], l[2]); split1(v.w, h[3], l[3]);
    ((uint2*)hi)[i] = *(uint2*)h;
    ((uint2*)lo)[i] = *(uint2*)l;
}
__global__ void cvt_hi(const float* __restrict__ s, __half* __restrict__ hi, int n4)
{
    int i = blockIdx.x * 256 + threadIdx.x;
    if (i >= n4) return;
    float4 v = ((const float4*)s)[i];
    __half h[4] = {__float2half_rn(v.x), __float2half_rn(v.y),
                   __float2half_rn(v.z), __float2half_rn(v.w)};
    ((uint2*)hi)[i] = *(uint2*)h;
}

__global__ void bias_gather(const float* a, const float* b, const float* c, float* o)
{
    const float* src[3] = {a, b, c};
    o[blockIdx.x * 1024 + threadIdx.x] = src[blockIdx.x][threadIdx.x];
}

// =====================================================================================
// channel LayerNorm -> fp16 hi/lo planes (up to 3)
// =====================================================================================
__global__ void ln3_kernel(const float* __restrict__ x, int nOut,
    const float* __restrict__ w0, const float* __restrict__ b0,
    const float* __restrict__ w1, const float* __restrict__ b1,
    const float* __restrict__ w2, const float* __restrict__ b2,
    __half* __restrict__ oHi, __half* __restrict__ oLo)
{
    const int dx   = threadIdx.x & 31;
    const int lane = threadIdx.x >> 5;
    const int d    = blockIdx.x * 32 + dx;
    const long base = (long)blockIdx.y * CD + d;

    float s = 0.f, ss = 0.f;
    for (int c = lane; c < CC; c += 8) {
        float v = x[base + (long)c * DD];
        s += v; ss += v * v;
    }
    __shared__ float sS[8][33], sQ[8][33];
    sS[lane][dx] = s; sQ[lane][dx] = ss;
    __syncthreads();
    if (lane == 0) {
        float ts = 0.f, tq = 0.f;
        #pragma unroll
        for (int i = 0; i < 8; i++) { ts += sS[i][dx]; tq += sQ[i][dx]; }
        float mean = ts * (1.0f / CC);
        float var  = tq * (1.0f / CC) - mean * mean;
        sS[0][dx] = mean;
        sQ[0][dx] = rsqrtf(var + 1e-6f);
    }
    __syncthreads();
    const float mean = sS[0][dx];
    const float rstd = sQ[0][dx];
    const float* W[3] = {w0, w1, w2};
    const float* Bv[3] = {b0, b1, b2};
    for (int c = lane; c < CC; c += 8) {
        long idx = base + (long)c * DD;
        float xn = (x[idx] - mean) * rstd;
        for (int p = 0; p < nOut; p++) {
            float v = W[p][c] * xn + Bv[p][c];
            __half h, l;
            split1(v, h, l);
            oHi[(long)p * BCD + idx] = h;
            oLo[(long)p * BCD + idx] = l;
        }
    }
}

// =====================================================================================
extern "C" void kernel_launch(void* const* d_in, const int* in_sizes, int n_in,
                              void* d_out, int out_size)
{
    const float* x1      = (const float*)d_in[0];
    const float* lnq_w   = (const float*)d_in[1];
    const float* lnq_b   = (const float*)d_in[2];
    const float* lnk_w   = (const float*)d_in[3];
    const float* lnk_b   = (const float*)d_in[4];
    const float* lnv_w   = (const float*)d_in[5];
    const float* lnv_b   = (const float*)d_in[6];
    const float* wq      = (const float*)d_in[7];
    const float* bq      = (const float*)d_in[8];
    const float* wk      = (const float*)d_in[9];
    const float* bk      = (const float*)d_in[10];
    const float* wv      = (const float*)d_in[11];
    const float* bv      = (const float*)d_in[12];
    const float* ffnln_w = (const float*)d_in[13];
    const float* ffnln_b = (const float*)d_in[14];
    const float* conv1_w = (const float*)d_in[15];
    const float* conv1_b = (const float*)d_in[16];
    const float* conv2_w = (const float*)d_in[17];
    const float* conv2_b = (const float*)d_in[18];

    __half *lnHi, *lnLo, *qkvHi, *qkvLo, *wHi;
    __half *c1wHi, *c1wLo, *c2wHi, *c2wLo, *xlHi, *xlLo, *h1Hi, *h1Lo;
    float *xb, *bqkv;
    cudaGetSymbolAddress((void**)&lnHi,  g_ln_hi);   cudaGetSymbolAddress((void**)&lnLo,  g_ln_lo);
    cudaGetSymbolAddress((void**)&qkvHi, g_qkv_hi);  cudaGetSymbolAddress((void**)&qkvLo, g_qkv_lo);
    cudaGetSymbolAddress((void**)&wHi,   g_w_hi);
    cudaGetSymbolAddress((void**)&c1wHi, g_c1w_hi);  cudaGetSymbolAddress((void**)&c1wLo, g_c1w_lo);
    cudaGetSymbolAddress((void**)&c2wHi, g_c2w_hi);  cudaGetSymbolAddress((void**)&c2wLo, g_c2w_lo);
    cudaGetSymbolAddress((void**)&xlHi,  g_xl_hi);   cudaGetSymbolAddress((void**)&xlLo,  g_xl_lo);
    cudaGetSymbolAddress((void**)&h1Hi,  g_h1_hi);   cudaGetSymbolAddress((void**)&h1Lo,  g_h1_lo);
    cudaGetSymbolAddress((void**)&xb,    g_x);
    cudaGetSymbolAddress((void**)&bqkv,  g_bqkv);

    float* outx = (float*)d_out;
    float* attn = outx + (long)BCD;

    // GEMM roles: A operand = hi/lo split (exact-ish); B operand = single fp16 (2-MMA)
    //   QKV : A=ln (hi/lo),  B=w single     -> q/k/v planes (hi/lo, fp16)
    //   PV  : A=attn (fp32 split in-kernel), B=v hi plane
    //   C1  : A=c1w (hi/lo), B=xl hi plane
    //   C2  : A=c2w (hi/lo), B=h1 hi plane
    auto kQKV = tc2_gemm<2, false, false, false, true,  false, false, false, true >;
    auto kPV  = tc2_gemm<2, true,  true,  false, false, false, true,  false, false>;
    auto kC1  = tc2_gemm<2, true,  false, true,  false, true,  false, false, true >;
    auto kC2  = tc2_gemm<2, true,  false, true,  false, false, true,  false, false>;
    const int SM_KB = 2 * (2 * 128 * 40 + 1 * 64 * 40) * 2;   // 51200
    const int SM_TR = 2 * (2 * 128 * 40 + 1 * 32 * 72) * 2;   // 50176
    const int SM_QS = (2 * 32 * 72 + 4 * 128 * 72) * 2 + 2 * 32 * 9 * 4;  // 85248
    cudaFuncSetAttribute(kQKV, cudaFuncAttributeMaxDynamicSharedMemorySize, SM_KB);
    cudaFuncSetAttribute(kPV,  cudaFuncAttributeMaxDynamicSharedMemorySize, SM_TR);
    cudaFuncSetAttribute(kC1,  cudaFuncAttributeMaxDynamicSharedMemorySize, SM_TR);
    cudaFuncSetAttribute(kC2,  cudaFuncAttributeMaxDynamicSharedMemorySize, SM_TR);
    cudaFuncSetAttribute(qk_softmax, cudaFuncAttributeMaxDynamicSharedMemorySize, SM_QS);

    // 0) weight converts + bias gather
    cvt_hi<<<CD / 4 / 256, 256>>>(wq, wHi,          CD / 4);
    cvt_hi<<<CD / 4 / 256, 256>>>(wk, wHi + CD,     CD / 4);
    cvt_hi<<<CD / 4 / 256, 256>>>(wv, wHi + 2 * CD, CD / 4);
    cvt_hilo<<<4 * CD / 4 / 256, 256>>>(conv1_w, c1wHi, c1wLo, 4 * CD / 4);
    cvt_hilo<<<4 * CD / 4 / 256, 256>>>(conv2_w, c2wHi, c2wLo, 4 * CD / 4);
    bias_gather<<<3, 1024>>>(bq, bk, bv, bqkv);

    // 1) QKV LayerNorms -> hi/lo planes
    dim3 lng(DD / 32, BB);
    ln3_kernel<<<lng, 256>>>(x1, 3, lnq_w, lnq_b, lnk_w, lnk_b, lnv_w, lnv_b, lnHi, lnLo);

    // 2) fused QKV linears (z = 0/1/2), 2-MMA
    dim3 gqkv(16, 32, 3);
    kQKV<<<gqkv, 128, SM_KB>>>(lnHi, lnLo, BCD, 1024, wHi, nullptr, 1, CD, 0, 1024,
                               nullptr, qkvHi, qkvLo, 1, BCD, 0, 1024,
                               nullptr, bqkv, 1024, 1.f, 4096, 1024, 1024);

    // 3+4) fused S = softmax_one(0.125 * Q K^T) -> attn output (3-MMA fp16)
    dim3 gqs(32, BB * HH);
    qk_softmax<<<gqs, 256, SM_QS>>>(qkvHi, qkvLo, qkvHi + BCD, qkvLo + BCD, attn);

    // 5) O = P V, scatter to x[b, i, h*64+e], fused residual add of x1 (2-MMA)
    dim3 gpv(1, 8, BB * HH);
    kPV<<<gpv, 128, SM_TR>>>(attn, nullptr, 1048576, 1024,
                             qkvHi + 2 * (long)BCD, nullptr, 1, 65536, 0, 64,
                             xb, nullptr, nullptr, 16, CD, 64, 1024,
                             x1, nullptr, 0, 1.f, 1024, 64, 1024);

    // 6) FFN LayerNorm -> xl hi/lo
    ln3_kernel<<<lng, 256>>>(xb, 1, ffnln_w, ffnln_b, nullptr, nullptr, nullptr, nullptr,
                             xlHi, xlLo);

    // 7) conv1: h1 = GELU(W1 @ xl_z + b1) (2-MMA)
    dim3 gc1(16, 32, BB);
    kC1<<<gc1, 128, SM_TR>>>(c1wHi, c1wLo, 0, 1024, xlHi, nullptr, 1, CD, 0, 1024,
                             nullptr, h1Hi, h1Lo, 1, (long)4096 * 1024, 0, 1024,
                             nullptr, conv1_b, 0, 1.f, 4096, 1024, 1024);

    // 8) conv2 + residual: out = x + (W2 @ h1_z + b2) (2-MMA)
    dim3 gc2(16, 8, BB);
    kC2<<<gc2, 128, SM_TR>>>(c2wHi, c2wLo, 0, 4096, h1Hi, nullptr, 1, (long)4096 * 1024, 0, 1024,
                             outx, nullptr, nullptr, 1, CD, 0, 1024,
                             xb, conv2_b, 0, 1.f, 1024, 1024, 4096);
}

// round 11
// speedup vs baseline: 1.4392x; 1.2064x over previous
#include <cuda_runtime.h>
#include <cuda_fp16.h>
#include <math.h>
#include <stdint.h>

#define BB   4
#define CC   1024
#define DD   1024
#define HH   16
#define CD   (CC*DD)          // 1048576
#define BCD  (BB*CD)          // 4194304
#define H1SZ (BB*4096*1024)   // 16777216

// ---------------- scratch (static __device__ arrays; no runtime alloc) ---------------
__device__ __half g_ln_hi[3*BCD],  g_ln_lo[3*BCD];
__device__ __half g_qkv_hi[3*BCD], g_qkv_lo[3*BCD];
__device__ __half g_w_hi[3*CD];
__device__ __half g_c1w_hi[4*CD];
__device__ __half g_c2w_hi[4*CD];
__device__ __half g_xl_hi[BCD];
__device__ __half g_h1_hi[H1SZ];
__device__ float g_x[BCD];
__device__ float g_bqkv[3*1024];

// =====================================================================================
// helpers
// =====================================================================================
__device__ __forceinline__ uint32_t smem_u32(const void* p) {
    uint32_t a;
    asm("{ .reg .u64 t; cvta.to.shared.u64 t, %1; cvt.u32.u64 %0, t; }" : "=r"(a) : "l"(p));
    return a;
}
__device__ __forceinline__ void cpa16(uint32_t s, const void* g) {
    asm volatile("cp.async.cg.shared.global [%0], [%1], 16;" :: "r"(s), "l"(g));
}
__device__ __forceinline__ void ldsm4(uint32_t addr, uint32_t& r0, uint32_t& r1,
                                      uint32_t& r2, uint32_t& r3) {
    asm volatile("ldmatrix.sync.aligned.m8n8.x4.shared.b16 {%0,%1,%2,%3}, [%4];"
                 : "=r"(r0), "=r"(r1), "=r"(r2), "=r"(r3) : "r"(addr));
}
__device__ __forceinline__ void ldsm4t(uint32_t addr, uint32_t& r0, uint32_t& r1,
                                       uint32_t& r2, uint32_t& r3) {
    asm volatile("ldmatrix.sync.aligned.m8n8.x4.trans.shared.b16 {%0,%1,%2,%3}, [%4];"
                 : "=r"(r0), "=r"(r1), "=r"(r2), "=r"(r3) : "r"(addr));
}
__device__ __forceinline__ void mma16816(float* c, const uint32_t* a, const uint32_t* b) {
    asm volatile(
        "mma.sync.aligned.m16n8k16.row.col.f32.f16.f16.f32 "
        "{%0,%1,%2,%3}, {%4,%5,%6,%7}, {%8,%9}, {%0,%1,%2,%3};"
        : "+f"(c[0]), "+f"(c[1]), "+f"(c[2]), "+f"(c[3])
        : "r"(a[0]), "r"(a[1]), "r"(a[2]), "r"(a[3]), "r"(b[0]), "r"(b[1]));
}
__device__ __forceinline__ void split1(float v, __half& h, __half& l) {
    h = __float2half_rn(v);
    l = __float2half_rn(v - __half2float(h));
}

// =====================================================================================
// Tensor-core GEMM: block 128x64, 4 warps (warp tile 64x32), BK=32, 2-stage cp.async
// (race-free ordering), 3 CTAs/SM.
//   NMMA=1: D = a * b                       (both single fp16; cheapest)
//   NMMA=2: D = (a_hi + a_lo) * b           (A hi/lo split)
//   NMMA=3: + a_hi*b_lo cross term          (fp32-class)
//   A: fp16 planes (M,K) K-contig (or fp32 if ACONV, rounded/split in-kernel)
//   B: BTRANS=0 -> (N,K) K-contig; BTRANS=1 -> (K,N) N-contig (ldsm .trans)
//   OMODE: 0 = fp32 out, 1 = fp16 hi/lo planes, 2 = fp16 single plane
// =====================================================================================
template<int NMMA, int OMODE, bool BTRANS, bool ACONV, bool BIAS_M, bool BIAS_N,
         bool GELUF, bool ADDF, bool SCALEF>
__global__ void __launch_bounds__(128, 3)
tc2_gemm(const void* Ahv, const __half* Alo, long strideA, int lda,
         const __half* Bhi, const __half* Blo,
         int bDiv, long bHi, long bLo, int ldb,
         float* Cf, __half* Chi, __half* Clo,
         int cDiv, long cHi, long cLo, int ldc,
         const float* Add, const float* bias, int biasZ,
         float alpha, int M, int N, int K)
{
    constexpr int BN  = 64;
    constexpr int BK  = 32;
    constexpr int SKA = 40;
    constexpr int SN  = BN + 8;                    // 72
    constexpr int ASZ = 128 * SKA;                 // 5120 elems per A plane
    constexpr int BSZ = BTRANS ? (BK * SN) : (BN * SKA);
    constexpr int APL = (NMMA >= 2) ? 2 : 1;
    constexpr int BPL = (NMMA == 3) ? 2 : 1;
    constexpr int STAGE = APL * ASZ + BPL * BSZ;
    constexpr int MF = 4;
    constexpr int NF = 4;

    extern __shared__ __half sm[];

    const int tid = threadIdx.x, wid = tid >> 5, lid = tid & 31;
    const int wm = wid >> 1, wn = wid & 1;
    const int z = blockIdx.z;
    const int row0 = blockIdx.y * 128, col0 = blockIdx.x * BN;

    const __half* Ahi = ACONV ? nullptr : ((const __half*)Ahv + (long)z * strideA);
    const __half* Alz = (ACONV || APL == 1) ? nullptr : (Alo + (long)z * strideA);
    const float* Af = ACONV ? ((const float*)Ahv + (long)z * strideA) : nullptr;
    Bhi += (long)(z / bDiv) * bHi + (long)(z % bDiv) * bLo;
    if (NMMA == 3) Blo += (long)(z / bDiv) * bHi + (long)(z % bDiv) * bLo;
    const long coff = (long)(z / cDiv) * cHi + (long)(z % cDiv) * cLo;
    if (BIAS_N || BIAS_M) bias += (long)z * biasZ;

    const uint32_t smBase = smem_u32(sm);
    const int nIt = K / BK;

    float acc[MF][NF][4];
#pragma unroll
    for (int i = 0; i < MF; i++)
#pragma unroll
        for (int j = 0; j < NF; j++)
#pragma unroll
            for (int r = 0; r < 4; r++) acc[i][j][r] = 0.f;

    float4 av[8];  // ACONV staging

    auto issueTile = [&](int it, int st) {
        const int k0 = it * BK;
        const uint32_t sbase = smBase + (uint32_t)(st * STAGE) * 2;
        if (!ACONV) {
#pragma unroll
            for (int pl = 0; pl < APL; pl++) {
                const __half* Ag = pl ? Alz : Ahi;
                const uint32_t sd = sbase + (uint32_t)(pl * ASZ) * 2;
#pragma unroll
                for (int i = 0; i < 4; i++) {
                    int idx = tid + (i << 7);
                    int r = idx >> 2, c8 = (idx & 3) << 3;
                    cpa16(sd + (uint32_t)(r * SKA + c8) * 2,
                          Ag + (long)(row0 + r) * lda + k0 + c8);
                }
            }
        }
        if (BTRANS) {
#pragma unroll
            for (int pl = 0; pl < BPL; pl++) {
                const __half* Bg = pl ? Blo : Bhi;
                const uint32_t sd = sbase + (uint32_t)(APL * ASZ + pl * BSZ) * 2;
#pragma unroll
                for (int i = 0; i < 2; i++) {
                    int idx = tid + (i << 7);
                    int k = idx >> 3, c8 = (idx & 7) << 3;
                    cpa16(sd + (uint32_t)(k * SN + c8) * 2,
                          Bg + (long)(k0 + k) * ldb + col0 + c8);
                }
            }
        } else {
#pragma unroll
            for (int pl = 0; pl < BPL; pl++) {
                const __half* Bg = pl ? Blo : Bhi;
                const uint32_t sd = sbase + (uint32_t)(APL * ASZ + pl * BSZ) * 2;
#pragma unroll
                for (int i = 0; i < 2; i++) {
                    int idx = tid + (i << 7);
                    int r = idx >> 2, c8 = (idx & 3) << 3;
                    cpa16(sd + (uint32_t)(r * SKA + c8) * 2,
                          Bg + (long)(col0 + r) * ldb + k0 + c8);
                }
            }
        }
    };
    auto ldgA = [&](int it) {
        const int k0 = it * BK;
#pragma unroll
        for (int i = 0; i < 8; i++) {
            int idx = tid + (i << 7);
            int r = idx >> 3, c4 = (idx & 7) << 2;
            av[i] = *(const float4*)(Af + (long)(row0 + r) * lda + k0 + c4);
        }
    };
    auto stsA = [&](int st) {
        __half* sAhi = sm + st * STAGE;
        __half* sAlo = sAhi + ASZ;
#pragma unroll
        for (int i = 0; i < 8; i++) {
            int idx = tid + (i << 7);
            int r = idx >> 3, c4 = (idx & 7) << 2;
            if (APL == 2) {
                __half h[4], l[4];
                split1(av[i].x, h[0], l[0]); split1(av[i].y, h[1], l[1]);
                split1(av[i].z, h[2], l[2]); split1(av[i].w, h[3], l[3]);
                *(uint2*)(sAhi + r * SKA + c4) = *(uint2*)h;
                *(uint2*)(sAlo + r * SKA + c4) = *(uint2*)l;
            } else {
                __half h[4] = {__float2half_rn(av[i].x), __float2half_rn(av[i].y),
                               __float2half_rn(av[i].z), __float2half_rn(av[i].w)};
                *(uint2*)(sAhi + r * SKA + c4) = *(uint2*)h;
            }
        }
    };

    if (ACONV) { ldgA(0); stsA(0); }
    issueTile(0, 0);
    asm volatile("cp.async.commit_group;");

    for (int it = 0; it < nIt; it++) {
        const int s = it & 1;
        asm volatile("cp.async.wait_group 0;");
        __syncthreads();
        if (it + 1 < nIt) {
            if (ACONV) ldgA(it + 1);
            issueTile(it + 1, s ^ 1);
            asm volatile("cp.async.commit_group;");
        }

        const uint32_t base = smBase + (uint32_t)(s * STAGE) * 2;
        const uint32_t aHiB = base, aLoB = base + ASZ * 2;
        const uint32_t bHiB = base + APL * ASZ * 2, bLoB = bHiB + BSZ * 2;

#pragma unroll
        for (int ks = 0; ks < 2; ks++) {
            uint32_t ah[MF][4], al[MF][4], bh[NF][2], bl[NF][2];
#pragma unroll
            for (int mf = 0; mf < MF; mf++) {
                uint32_t off = (uint32_t)((wm * 64 + mf * 16 + (lid & 15)) * SKA
                                          + ks * 16 + (lid >> 4) * 8) * 2;
                ldsm4(aHiB + off, ah[mf][0], ah[mf][1], ah[mf][2], ah[mf][3]);
                if (APL == 2)
                    ldsm4(aLoB + off, al[mf][0], al[mf][1], al[mf][2], al[mf][3]);
            }
            if (BTRANS) {
#pragma unroll
                for (int p = 0; p < NF / 2; p++) {
                    uint32_t off = (uint32_t)((ks * 16 + (lid & 15)) * SN
                                              + wn * 32 + p * 16 + (lid >> 4) * 8) * 2;
                    ldsm4t(bHiB + off, bh[2*p][0], bh[2*p][1], bh[2*p+1][0], bh[2*p+1][1]);
                    if (NMMA == 3)
                        ldsm4t(bLoB + off, bl[2*p][0], bl[2*p][1], bl[2*p+1][0], bl[2*p+1][1]);
                }
            } else {
#pragma unroll
                for (int p = 0; p < NF / 2; p++) {
                    uint32_t off = (uint32_t)((wn * 32 + p * 16 + (lid & 7) + (lid >> 4) * 8) * SKA
                                              + ks * 16 + ((lid >> 3) & 1) * 8) * 2;
                    ldsm4(bHiB + off, bh[2*p][0], bh[2*p][1], bh[2*p+1][0], bh[2*p+1][1]);
                    if (NMMA == 3)
                        ldsm4(bLoB + off, bl[2*p][0], bl[2*p][1], bl[2*p+1][0], bl[2*p+1][1]);
                }
            }
#pragma unroll
            for (int mf = 0; mf < MF; mf++)
#pragma unroll
                for (int nf = 0; nf < NF; nf++)
                    mma16816(acc[mf][nf], ah[mf], bh[nf]);
            if (NMMA == 3) {
#pragma unroll
                for (int mf = 0; mf < MF; mf++)
#pragma unroll
                    for (int nf = 0; nf < NF; nf++)
                        mma16816(acc[mf][nf], ah[mf], bl[nf]);
            }
            if (NMMA >= 2) {
#pragma unroll
                for (int mf = 0; mf < MF; mf++)
#pragma unroll
                    for (int nf = 0; nf < NF; nf++)
                        mma16816(acc[mf][nf], al[mf], bh[nf]);
            }
        }
        if (ACONV && it + 1 < nIt) stsA(s ^ 1);
    }

    // ---- epilogue ----
    float* Cp = (OMODE == 0) ? (Cf + coff) : nullptr;
    __half* ChP = (OMODE != 0) ? (Chi + coff) : nullptr;
    __half* ClP = (OMODE == 1) ? (Clo + coff) : nullptr;
    const float* Ap2 = ADDF ? (Add + coff) : nullptr;
    const int rBase = row0 + wm * 64 + (lid >> 2);
    const int cBase = col0 + wn * 32 + (lid & 3) * 2;
#pragma unroll
    for (int mf = 0; mf < MF; mf++) {
#pragma unroll
        for (int half = 0; half < 2; half++) {
            const int gr = rBase + mf * 16 + half * 8;
            const float bm = BIAS_M ? bias[gr] : 0.f;
#pragma unroll
            for (int nf = 0; nf < NF; nf++) {
                const int gc = cBase + nf * 8;
                float v0 = acc[mf][nf][half * 2 + 0];
                float v1 = acc[mf][nf][half * 2 + 1];
                if (SCALEF) { v0 *= alpha; v1 *= alpha; }
                if (BIAS_M) { v0 += bm; v1 += bm; }
                if (BIAS_N) { v0 += bias[gc]; v1 += bias[gc + 1]; }
                if (GELUF) {
                    v0 = 0.5f * v0 * (1.0f + erff(v0 * 0.70710678118654752f));
                    v1 = 0.5f * v1 * (1.0f + erff(v1 * 0.70710678118654752f));
                }
                long off = (long)gr * ldc + gc;
                if (ADDF) { v0 += Ap2[off]; v1 += Ap2[off + 1]; }
                if (OMODE == 1) {
                    __half h0, l0, h1, l1;
                    split1(v0, h0, l0); split1(v1, h1, l1);
                    __half hp[2] = {h0, h1}, lp[2] = {l0, l1};
                    *(uint32_t*)(ChP + off) = *(uint32_t*)hp;
                    *(uint32_t*)(ClP + off) = *(uint32_t*)lp;
                } else if (OMODE == 2) {
                    __half hp[2] = {__float2half_rn(v0), __float2half_rn(v1)};
                    *(uint32_t*)(ChP + off) = *(uint32_t*)hp;
                } else {
                    *(float2*)(Cp + off) = make_float2(v0, v1);
                }
            }
        }
    }
}

// =====================================================================================
// Fused QK^T * 0.125 + softmax-one -> attn out (unchanged from R10, known good).
// =====================================================================================
__global__ void __launch_bounds__(256, 1)
qk_softmax(const __half* __restrict__ qHi, const __half* __restrict__ qLo,
           const __half* __restrict__ kHi, const __half* __restrict__ kLo,
           float* __restrict__ attn)
{
    constexpr int SK = 72;
    constexpr int QPL = 32 * SK;
    constexpr int KPL = 128 * SK;
    extern __shared__ __half sm[];
    float* redA = (float*)(sm + 2 * QPL + 4 * KPL);
    float* redB = redA + 32 * 9;

    const int tid = threadIdx.x, wid = tid >> 5, lid = tid & 31;
    const int z = blockIdx.y;
    const int row0 = blockIdx.x * 32;
    const __half* Qh = qHi + (long)z * 65536;
    const __half* Ql = qLo + (long)z * 65536;
    const __half* Kh = kHi + (long)z * 65536;
    const __half* Kl = kLo + (long)z * 65536;
    attn += (long)z * 1048576;

    const uint32_t smBase = smem_u32(sm);

    {
        int r = tid >> 3, c8 = (tid & 7) << 3;
        cpa16(smBase + (uint32_t)(r * SK + c8) * 2,        Qh + (long)(row0 + r) * 64 + c8);
        cpa16(smBase + (uint32_t)(QPL + r * SK + c8) * 2,  Ql + (long)(row0 + r) * 64 + c8);
    }
    auto issueK = [&](int ch, int st) {
        const uint32_t sb = smBase + (uint32_t)(2 * QPL + st * 2 * KPL) * 2;
#pragma unroll
        for (int pl = 0; pl < 2; pl++) {
            const __half* Kg = pl ? Kl : Kh;
            const uint32_t sd = sb + (uint32_t)(pl * KPL) * 2;
#pragma unroll
            for (int i = 0; i < 4; i++) {
                int idx = tid + (i << 8);
                int r = idx >> 3, c8 = (idx & 7) << 3;
                cpa16(sd + (uint32_t)(r * SK + c8) * 2,
                      Kg + (long)(ch * 128 + r) * 64 + c8);
            }
        }
    };
    issueK(0, 0);
    asm volatile("cp.async.commit_group;");

    float acc[2][8][2][4];
#pragma unroll
    for (int mf = 0; mf < 2; mf++)
#pragma unroll
        for (int ch = 0; ch < 8; ch++)
#pragma unroll
            for (int nf = 0; nf < 2; nf++)
#pragma unroll
                for (int r = 0; r < 4; r++) acc[mf][ch][nf][r] = 0.f;

    uint32_t aH[4][2][4], aL[4][2][4];

    for (int ch = 0; ch < 8; ch++) {
        asm volatile("cp.async.wait_group 0;");
        __syncthreads();
        if (ch + 1 < 8) {
            issueK(ch + 1, (ch + 1) & 1);
            asm volatile("cp.async.commit_group;");
        }
        if (ch == 0) {
#pragma unroll
            for (int ks = 0; ks < 4; ks++)
#pragma unroll
                for (int mf = 0; mf < 2; mf++) {
                    uint32_t off = (uint32_t)((mf * 16 + (lid & 15)) * SK
                                              + ks * 16 + (lid >> 4) * 8) * 2;
                    ldsm4(smBase + off,           aH[ks][mf][0], aH[ks][mf][1],
                                                  aH[ks][mf][2], aH[ks][mf][3]);
                    ldsm4(smBase + QPL * 2 + off, aL[ks][mf][0], aL[ks][mf][1],
                                                  aL[ks][mf][2], aL[ks][mf][3]);
                }
        }
        const int st = ch & 1;
        const uint32_t kHiB = smBase + (uint32_t)(2 * QPL + st * 2 * KPL) * 2;
        const uint32_t kLoB = kHiB + (uint32_t)KPL * 2;
        const int wn = wid;
#pragma unroll
        for (int ks = 0; ks < 4; ks++) {
            uint32_t bh[2][2], bl[2][2];
            uint32_t off = (uint32_t)((wn * 16 + (lid & 7) + (lid >> 4) * 8) * SK
                                      + ks * 16 + ((lid >> 3) & 1) * 8) * 2;
            ldsm4(kHiB + off, bh[0][0], bh[0][1], bh[1][0], bh[1][1]);
            ldsm4(kLoB + off, bl[0][0], bl[0][1], bl[1][0], bl[1][1]);
#pragma unroll
            for (int mf = 0; mf < 2; mf++)
#pragma unroll
                for (int nf = 0; nf < 2; nf++) {
                    mma16816(acc[mf][ch][nf], aH[ks][mf], bh[nf]);
                    mma16816(acc[mf][ch][nf], aH[ks][mf], bl[nf]);
                    mma16816(acc[mf][ch][nf], aL[ks][mf], bh[nf]);
                }
        }
    }

    const int rq = lid >> 2, cq = lid & 3;
    const int wn = wid;
#pragma unroll
    for (int mf = 0; mf < 2; mf++)
#pragma unroll
        for (int ch = 0; ch < 8; ch++)
#pragma unroll
            for (int nf = 0; nf < 2; nf++)
#pragma unroll
                for (int r = 0; r < 4; r++) acc[mf][ch][nf][r] *= 0.125f;

    float mx[2][2];
#pragma unroll
    for (int mf = 0; mf < 2; mf++)
#pragma unroll
        for (int half = 0; half < 2; half++) {
            float m = -1e30f;
#pragma unroll
            for (int ch = 0; ch < 8; ch++)
#pragma unroll
                for (int nf = 0; nf < 2; nf++)
                    m = fmaxf(m, fmaxf(acc[mf][ch][nf][half*2], acc[mf][ch][nf][half*2+1]));
            m = fmaxf(m, __shfl_xor_sync(0xffffffffu, m, 1));
            m = fmaxf(m, __shfl_xor_sync(0xffffffffu, m, 2));
            mx[mf][half] = m;
        }
    if (cq == 0) {
#pragma unroll
        for (int mf = 0; mf < 2; mf++)
#pragma unroll
            for (int half = 0; half < 2; half++)
                redA[(mf * 16 + half * 8 + rq) * 9 + wid] = mx[mf][half];
    }
    __syncthreads();
#pragma unroll
    for (int mf = 0; mf < 2; mf++)
#pragma unroll
        for (int half = 0; half < 2; half++) {
            float m = -1e30f;
            const float* rr = redA + (mf * 16 + half * 8 + rq) * 9;
#pragma unroll
            for (int w = 0; w < 8; w++) m = fmaxf(m, rr[w]);
            mx[mf][half] = m;
        }

    float sum[2][2] = {{0.f, 0.f}, {0.f, 0.f}};
#pragma unroll
    for (int mf = 0; mf < 2; mf++)
#pragma unroll
        for (int half = 0; half < 2; half++) {
            const float m = mx[mf][half];
            float s = 0.f;
#pragma unroll
            for (int ch = 0; ch < 8; ch++)
#pragma unroll
                for (int nf = 0; nf < 2; nf++) {
                    float e0 = __expf(acc[mf][ch][nf][half*2]     - m);
                    float e1 = __expf(acc[mf][ch][nf][half*2 + 1] - m);
                    acc[mf][ch][nf][half*2]     = e0;
                    acc[mf][ch][nf][half*2 + 1] = e1;
                    s += e0 + e1;
                }
            s += __shfl_xor_sync(0xffffffffu, s, 1);
            s += __shfl_xor_sync(0xffffffffu, s, 2);
            sum[mf][half] = s;
        }
    if (cq == 0) {
#pragma unroll
        for (int mf = 0; mf < 2; mf++)
#pragma unroll
            for (int half = 0; half < 2; half++)
                redB[(mf * 16 + half * 8 + rq) * 9 + wid] = sum[mf][half];
    }
    __syncthreads();
#pragma unroll
    for (int mf = 0; mf < 2; mf++)
#pragma unroll
        for (int half = 0; half < 2; half++) {
            float s = 0.f;
            const float* rr = redB + (mf * 16 + half * 8 + rq) * 9;
#pragma unroll
            for (int w = 0; w < 8; w++) s += rr[w];
            sum[mf][half] = 1.0f / (1.0f + s);
        }

#pragma unroll
    for (int mf = 0; mf < 2; mf++)
#pragma unroll
        for (int half = 0; half < 2; half++) {
            const int gr = row0 + mf * 16 + half * 8 + rq;
            const float inv = sum[mf][half];
#pragma unroll
            for (int ch = 0; ch < 8; ch++)
#pragma unroll
                for (int nf = 0; nf < 2; nf++) {
                    const int gc = ch * 128 + wn * 16 + nf * 8 + cq * 2;
                    *(float2*)(attn + (long)gr * 1024 + gc) =
                        make_float2(acc[mf][ch][nf][half*2] * inv,
                                    acc[mf][ch][nf][half*2+1] * inv);
                }
        }
}

// =====================================================================================
__global__ void cvt_hilo(const float* __restrict__ s, __half* __restrict__ hi,
                         __half* __restrict__ lo, int n4)
{
    int i = blockIdx.x * 256 + threadIdx.x;
    if (i >= n4) return;
    float4 v = ((const float4*)s)[i];
    __half h[4], l[4];
    split1(v.x, h[0], l[0]); split1(v.y, h[1], l[1]);
    split1(v.z, h[2], l[2]); split1(v.w, h[3], l[3]);
    ((uint2*)hi)[i] = *(uint2*)h;
    ((uint2*)lo)[i] = *(uint2*)l;
}
__global__ void cvt_hi(const float* __restrict__ s, __half* __restrict__ hi, int n4)
{
    int i = blockIdx.x * 256 + threadIdx.x;
    if (i >= n4) return;
    float4 v = ((const float4*)s)[i];
    __half h[4] = {__float2half_rn(v.x), __float2half_rn(v.y),
                   __float2half_rn(v.z), __float2half_rn(v.w)};
    ((uint2*)hi)[i] = *(uint2*)h;
}

__global__ void bias_gather(const float* a, const float* b, const float* c, float* o)
{
    const float* src[3] = {a, b, c};
    o[blockIdx.x * 1024 + threadIdx.x] = src[blockIdx.x][threadIdx.x];
}

// =====================================================================================
// channel LayerNorm -> fp16 hi(/lo) planes (up to 3); lo written only if oLo != null
// =====================================================================================
__global__ void ln3_kernel(const float* __restrict__ x, int nOut,
    const float* __restrict__ w0, const float* __restrict__ b0,
    const float* __restrict__ w1, const float* __restrict__ b1,
    const float* __restrict__ w2, const float* __restrict__ b2,
    __half* __restrict__ oHi, __half* __restrict__ oLo)
{
    const int dx   = threadIdx.x & 31;
    const int lane = threadIdx.x >> 5;
    const int d    = blockIdx.x * 32 + dx;
    const long base = (long)blockIdx.y * CD + d;

    float s = 0.f, ss = 0.f;
    for (int c = lane; c < CC; c += 8) {
        float v = x[base + (long)c * DD];
        s += v; ss += v * v;
    }
    __shared__ float sS[8][33], sQ[8][33];
    sS[lane][dx] = s; sQ[lane][dx] = ss;
    __syncthreads();
    if (lane == 0) {
        float ts = 0.f, tq = 0.f;
        #pragma unroll
        for (int i = 0; i < 8; i++) { ts += sS[i][dx]; tq += sQ[i][dx]; }
        float mean = ts * (1.0f / CC);
        float var  = tq * (1.0f / CC) - mean * mean;
        sS[0][dx] = mean;
        sQ[0][dx] = rsqrtf(var + 1e-6f);
    }
    __syncthreads();
    const float mean = sS[0][dx];
    const float rstd = sQ[0][dx];
    const float* W[3] = {w0, w1, w2};
    const float* Bv[3] = {b0, b1, b2};
    for (int c = lane; c < CC; c += 8) {
        long idx = base + (long)c * DD;
        float xn = (x[idx] - mean) * rstd;
        for (int p = 0; p < nOut; p++) {
            float v = W[p][c] * xn + Bv[p][c];
            if (oLo) {
                __half h, l;
                split1(v, h, l);
                oHi[(long)p * BCD + idx] = h;
                oLo[(long)p * BCD + idx] = l;
            } else {
                oHi[(long)p * BCD + idx] = __float2half_rn(v);
            }
        }
    }
}

// =====================================================================================
extern "C" void kernel_launch(void* const* d_in, const int* in_sizes, int n_in,
                              void* d_out, int out_size)
{
    const float* x1      = (const float*)d_in[0];
    const float* lnq_w   = (const float*)d_in[1];
    const float* lnq_b   = (const float*)d_in[2];
    const float* lnk_w   = (const float*)d_in[3];
    const float* lnk_b   = (const float*)d_in[4];
    const float* lnv_w   = (const float*)d_in[5];
    const float* lnv_b   = (const float*)d_in[6];
    const float* wq      = (const float*)d_in[7];
    const float* bq      = (const float*)d_in[8];
    const float* wk      = (const float*)d_in[9];
    const float* bk      = (const float*)d_in[10];
    const float* wv      = (const float*)d_in[11];
    const float* bv      = (const float*)d_in[12];
    const float* ffnln_w = (const float*)d_in[13];
    const float* ffnln_b = (const float*)d_in[14];
    const float* conv1_w = (const float*)d_in[15];
    const float* conv1_b = (const float*)d_in[16];
    const float* conv2_w = (const float*)d_in[17];
    const float* conv2_b = (const float*)d_in[18];

    __half *lnHi, *lnLo, *qkvHi, *qkvLo, *wHi;
    __half *c1wHi, *c2wHi, *xlHi, *h1Hi;
    float *xb, *bqkv;
    cudaGetSymbolAddress((void**)&lnHi,  g_ln_hi);   cudaGetSymbolAddress((void**)&lnLo,  g_ln_lo);
    cudaGetSymbolAddress((void**)&qkvHi, g_qkv_hi);  cudaGetSymbolAddress((void**)&qkvLo, g_qkv_lo);
    cudaGetSymbolAddress((void**)&wHi,   g_w_hi);
    cudaGetSymbolAddress((void**)&c1wHi, g_c1w_hi);
    cudaGetSymbolAddress((void**)&c2wHi, g_c2w_hi);
    cudaGetSymbolAddress((void**)&xlHi,  g_xl_hi);
    cudaGetSymbolAddress((void**)&h1Hi,  g_h1_hi);
    cudaGetSymbolAddress((void**)&xb,    g_x);
    cudaGetSymbolAddress((void**)&bqkv,  g_bqkv);

    float* outx = (float*)d_out;
    float* attn = outx + (long)BCD;

    // GEMM precision plan:
    //   QKV : NMMA=2 (A=ln hi/lo, B=w single) -> q/k/v hi/lo (needed by qk_softmax)
    //   PV  : NMMA=1 (A=attn fp32 rounded in-kernel, B=v hi)
    //   C1  : NMMA=1 (A=c1w single, B=xl single) -> h1 single fp16
    //   C2  : NMMA=1 (A=c2w single, B=h1 single) -> fp32 + residual
    auto kQKV = tc2_gemm<2, 1, false, false, false, true,  false, false, false>;
    auto kPV  = tc2_gemm<1, 0, true,  true,  false, false, false, true,  false>;
    auto kC1  = tc2_gemm<1, 2, true,  false, true,  false, true,  false, false>;
    auto kC2  = tc2_gemm<1, 0, true,  false, true,  false, false, true,  false>;
    const int SM_KB  = 2 * (2 * 128 * 40 + 1 * 64 * 40) * 2;  // 51200 (QKV)
    const int SM_1TR = 2 * (1 * 128 * 40 + 1 * 32 * 72) * 2;  // 29696 (PV/C1/C2)
    const int SM_QS = (2 * 32 * 72 + 4 * 128 * 72) * 2 + 2 * 32 * 9 * 4;  // 85248
    cudaFuncSetAttribute(kQKV, cudaFuncAttributeMaxDynamicSharedMemorySize, SM_KB);
    cudaFuncSetAttribute(kPV,  cudaFuncAttributeMaxDynamicSharedMemorySize, SM_1TR);
    cudaFuncSetAttribute(kC1,  cudaFuncAttributeMaxDynamicSharedMemorySize, SM_1TR);
    cudaFuncSetAttribute(kC2,  cudaFuncAttributeMaxDynamicSharedMemorySize, SM_1TR);
    cudaFuncSetAttribute(qk_softmax, cudaFuncAttributeMaxDynamicSharedMemorySize, SM_QS);

    // 0) weight converts + bias gather (single fp16 planes everywhere)
    cvt_hi<<<CD / 4 / 256, 256>>>(wq, wHi,          CD / 4);
    cvt_hi<<<CD / 4 / 256, 256>>>(wk, wHi + CD,     CD / 4);
    cvt_hi<<<CD / 4 / 256, 256>>>(wv, wHi + 2 * CD, CD / 4);
    cvt_hi<<<4 * CD / 4 / 256, 256>>>(conv1_w, c1wHi, 4 * CD / 4);
    cvt_hi<<<4 * CD / 4 / 256, 256>>>(conv2_w, c2wHi, 4 * CD / 4);
    bias_gather<<<3, 1024>>>(bq, bk, bv, bqkv);

    // 1) QKV LayerNorms -> hi/lo planes
    dim3 lng(DD / 32, BB);
    ln3_kernel<<<lng, 256>>>(x1, 3, lnq_w, lnq_b, lnk_w, lnk_b, lnv_w, lnv_b, lnHi, lnLo);

    // 2) fused QKV linears (z = 0/1/2), 2-MMA, outputs hi/lo
    dim3 gqkv(16, 32, 3);
    kQKV<<<gqkv, 128, SM_KB>>>(lnHi, lnLo, BCD, 1024, wHi, nullptr, 1, CD, 0, 1024,
                               nullptr, qkvHi, qkvLo, 1, BCD, 0, 1024,
                               nullptr, bqkv, 1024, 1.f, 4096, 1024, 1024);

    // 3+4) fused S = softmax_one(0.125 * Q K^T) -> attn output (3-MMA fp16)
    dim3 gqs(32, BB * HH);
    qk_softmax<<<gqs, 256, SM_QS>>>(qkvHi, qkvLo, qkvHi + BCD, qkvLo + BCD, attn);

    // 5) O = P V (1-MMA), scatter to x[b, i, h*64+e], fused residual add of x1
    dim3 gpv(1, 8, BB * HH);
    kPV<<<gpv, 128, SM_1TR>>>(attn, nullptr, 1048576, 1024,
                              qkvHi + 2 * (long)BCD, nullptr, 1, 65536, 0, 64,
                              xb, nullptr, nullptr, 16, CD, 64, 1024,
                              x1, nullptr, 0, 1.f, 1024, 64, 1024);

    // 6) FFN LayerNorm -> xl single plane
    ln3_kernel<<<lng, 256>>>(xb, 1, ffnln_w, ffnln_b, nullptr, nullptr, nullptr, nullptr,
                             xlHi, nullptr);

    // 7) conv1: h1 = GELU(W1 @ xl_z + b1) (1-MMA, single fp16 out)
    dim3 gc1(16, 32, BB);
    kC1<<<gc1, 128, SM_1TR>>>(c1wHi, nullptr, 0, 1024, xlHi, nullptr, 1, CD, 0, 1024,
                              nullptr, h1Hi, nullptr, 1, (long)4096 * 1024, 0, 1024,
                              nullptr, conv1_b, 0, 1.f, 4096, 1024, 1024);

    // 8) conv2 + residual: out = x + (W2 @ h1_z + b2) (1-MMA)
    dim3 gc2(16, 8, BB);
    kC2<<<gc2, 128, SM_1TR>>>(c2wHi, nullptr, 0, 4096, h1Hi, nullptr, 1, (long)4096 * 1024, 0, 1024,
                              outx, nullptr, nullptr, 1, CD, 0, 1024,
                              xb, conv2_b, 0, 1.f, 1024, 1024, 4096);
}